// round 10
// baseline (speedup 1.0000x reference)
#include <cuda_runtime.h>

#define Bn 1024
#define Tn 128
#define Hd 64
#define NZv 5
#define ACTD 20
#define Rr 8
#define SCAN_BLOCKS 128
#define EPS_T_BLOCKS 256                     // 256 blocks x 256 threads = 65536 outputs per timestep
#define EPS_TOTAL ((Tn + 1) * EPS_T_BLOCKS)  // 33024 eps blocks, bid [0, EPS_TOTAL)

typedef unsigned long long ull;

// ---------------- device scratch (static allocation only) ----------------
__device__ float g_eps[(size_t)(Tn + 1) * Bn * Hd];     // (T+1,B,H)
__device__ float g_kld[Bn];
__device__ int   g_done[Tn + 1];                        // zero-init at load; reset by last block
__device__ int   g_scan_done;                           // ditto
__device__ unsigned g_one = 1;   // runtime-opaque 1: forces adds onto IMAD (fma pipe)

// ---------------- f32x2 packed helpers ----------------
__device__ __forceinline__ ull pk2(float lo, float hi) {
    ull r; asm("mov.b64 %0, {%1, %2};" : "=l"(r) : "f"(lo), "f"(hi)); return r;
}
__device__ __forceinline__ void unpk2(ull v, float& lo, float& hi) {
    asm("mov.b64 {%0, %1}, %2;" : "=f"(lo), "=f"(hi) : "l"(v));
}
__device__ __forceinline__ ull pki2(unsigned lo, unsigned hi) {
    ull r; asm("mov.b64 %0, {%1, %2};" : "=l"(r) : "r"(lo), "r"(hi)); return r;
}
__device__ __forceinline__ ull fma2(ull a, ull b, ull c) {
    ull d; asm("fma.rn.f32x2 %0, %1, %2, %3;" : "=l"(d) : "l"(a), "l"(b), "l"(c)); return d;
}
__device__ __forceinline__ ull add2(ull a, ull b) {
    ull d; asm("add.rn.f32x2 %0, %1, %2;" : "=l"(d) : "l"(a), "l"(b)); return d;
}
__device__ __forceinline__ ull dup2(float x) { return pk2(x, x); }

// ---------------- math helpers ----------------
__device__ __forceinline__ float softplusf(float x) {
    return fmaxf(x, 0.0f) + log1pf(expf(-fabsf(x)));
}
__device__ __forceinline__ float sigmoidf(float x) {
    return 1.0f / (1.0f + expf(-x));
}

// add via IMAD so it issues on the fma pipe (alu pipe is the bottleneck)
__device__ __forceinline__ unsigned imadd(unsigned a, unsigned b, unsigned one) {
    unsigned d;
    asm("mad.lo.u32 %0, %1, %2, %3;" : "=r"(d) : "r"(a), "r"(one), "r"(b));
    return d;
}

// scalar Giles main-branch poly (mirrors packed order exactly)
__device__ __forceinline__ float poly_main(float wk) {
    float p = 2.81022636e-08f;
    p = fmaf(p, wk, 3.43273939e-07f);
    p = fmaf(p, wk, -3.5233877e-06f);
    p = fmaf(p, wk, -4.39150654e-06f);
    p = fmaf(p, wk, 0.00021858087f);
    p = fmaf(p, wk, -0.00125372503f);
    p = fmaf(p, wk, -0.00417768164f);
    p = fmaf(p, wk, 0.246640727f);
    p = fmaf(p, wk, 1.50140941f);
    return p;
}
__device__ __forceinline__ float poly_tail(float w) {
    float ws = sqrtf(w) - 3.0f;
    float p = -0.000200214257f;
    p = fmaf(p, ws, 0.000100950558f);
    p = fmaf(p, ws, 0.00134934322f);
    p = fmaf(p, ws, -0.00367342844f);
    p = fmaf(p, ws, 0.00573950773f);
    p = fmaf(p, ws, -0.0076224613f);
    p = fmaf(p, ws, 0.00943887047f);
    p = fmaf(p, ws, 1.00167406f);
    p = fmaf(p, ws, 2.83297682f);
    return p;
}

// general threefry (prologue key fold only)
__device__ __forceinline__ uint2 threefry2x32(unsigned k0, unsigned k1,
                                              unsigned x0, unsigned x1) {
    unsigned ks2 = k0 ^ k1 ^ 0x1BD11BDAu;
#define TF_RND(r) { x0 += x1; x1 = __funnelshift_l(x1, x1, r); x1 ^= x0; }
    x0 += k0; x1 += k1;
    TF_RND(13) TF_RND(15) TF_RND(26) TF_RND(6)
    x0 += k1;  x1 += ks2 + 1u;
    TF_RND(17) TF_RND(29) TF_RND(16) TF_RND(24)
    x0 += ks2; x1 += k0 + 2u;
    TF_RND(13) TF_RND(15) TF_RND(26) TF_RND(6)
    x0 += k0;  x1 += k1 + 3u;
    TF_RND(17) TF_RND(29) TF_RND(16) TF_RND(24)
    x0 += k1;  x1 += ks2 + 4u;
    TF_RND(13) TF_RND(15) TF_RND(26) TF_RND(6)
    x0 += ks2; x1 += k0 + 5u;
#undef TF_RND
    uint2 r; r.x = x0; r.y = x1; return r;
}

// hot path: counter word0 == 0, x1 init = e + k1d (chain offset pre-folded into k1d),
// integer adds on the fma pipe; returns y0 ^ y1
__device__ __forceinline__ unsigned tf_xor(
    unsigned k0, unsigned k1, unsigned ks2,
    unsigned c1, unsigned c2, unsigned c3, unsigned c4, unsigned c5,
    unsigned e, unsigned k1d, unsigned one)
{
    unsigned x0 = k0;
    unsigned x1 = imadd(e, k1d, one);
#define TF_RND(r) { x0 = imadd(x1, x0, one); x1 = __funnelshift_l(x1, x1, r); x1 ^= x0; }
    TF_RND(13) TF_RND(15) TF_RND(26) TF_RND(6)
    x0 = imadd(k1, x0, one);  x1 = imadd(c1, x1, one);
    TF_RND(17) TF_RND(29) TF_RND(16) TF_RND(24)
    x0 = imadd(ks2, x0, one); x1 = imadd(c2, x1, one);
    TF_RND(13) TF_RND(15) TF_RND(26) TF_RND(6)
    x0 = imadd(k0, x0, one);  x1 = imadd(c3, x1, one);
    TF_RND(17) TF_RND(29) TF_RND(16) TF_RND(24)
    x0 = imadd(k1, x0, one);  x1 = imadd(c4, x1, one);
    TF_RND(13) TF_RND(15) TF_RND(26) TF_RND(6)
    x0 = imadd(ks2, x0, one); x1 = imadd(c5, x1, one);
#undef TF_RND
    return x0 ^ x1;
}

// mantissa word via funnel shift: (bits>>9) | 0x3F800000 in ONE SHF
__device__ __forceinline__ unsigned mant(unsigned bits) {
    return __funnelshift_r(bits, 0x7Fu, 9);
}

// ============================================================================
// EPS role: one thread = one (t, b, z) output, 1000 samples, packed f32x2 path
// ============================================================================
__device__ __noinline__ void eps_role(int eb) {
    const int tid = threadIdx.x;
    const int t = eb >> 8;                   // 256 blocks per timestep
    const unsigned bz = (unsigned)((eb & 255) * 256 + tid);
    const int gid = t * (Bn * Hd) + (int)bz;

    const unsigned one = g_one;
    uint2 kk = threefry2x32(0u, 42u, 0u, (unsigned)t);   // fold_in(key(42), t)
    const unsigned k0 = kk.x, k1 = kk.y;
    const unsigned ks2 = k0 ^ k1 ^ 0x1BD11BDAu;
    const unsigned c1 = ks2 + 1u, c2 = k0 + 2u, c3 = k1 + 3u,
                   c4 = ks2 + 4u, c5 = k0 + 5u;
    const unsigned k1d0 = k1, k1d1 = k1 + 65536u,
                   k1d2 = k1 + 131072u, k1d3 = k1 + 196608u;

    // packed constants
    const ull NEGONE2  = dup2(-1.0f);
    const ull TWO2     = dup2(2.0f);
    const ull NEGP2    = dup2(-0.99999994f);
    const ull NEGLN2_2 = dup2(-0.69314718f);
    const ull M2P5_2   = dup2(-2.5f);
    const ull P0 = dup2(2.81022636e-08f);
    const ull P1 = dup2(3.43273939e-07f);
    const ull P2 = dup2(-3.5233877e-06f);
    const ull P3 = dup2(-4.39150654e-06f);
    const ull P4 = dup2(0.00021858087f);
    const ull P5 = dup2(-0.00125372503f);
    const ull P6 = dup2(-0.00417768164f);
    const ull P7 = dup2(0.246640727f);
    const ull P8 = dup2(1.50140941f);

    ull sumA = 0ull, sumB = 0ull;            // packed (0.0f, 0.0f)
    unsigned e = bz;
    const unsigned step = 262144u;

    #pragma unroll 2
    for (int s = 0; s < 250; s++) {
        unsigned b0 = tf_xor(k0, k1, ks2, c1, c2, c3, c4, c5, e, k1d0, one);
        unsigned b1 = tf_xor(k0, k1, ks2, c1, c2, c3, c4, c5, e, k1d1, one);
        unsigned b2 = tf_xor(k0, k1, ks2, c1, c2, c3, c4, c5, e, k1d2, one);
        unsigned b3 = tf_xor(k0, k1, ks2, c1, c2, c3, c4, c5, e, k1d3, one);

        // mantissa insert (1 SHF/lane), then packed float path (bit-identical to ref)
        ull gA = pki2(mant(b0), mant(b1));
        ull gB = pki2(mant(b2), mant(b3));
        ull fA = add2(gA, NEGONE2);          // exact: g-1 (Sterbenz)
        ull fB = add2(gB, NEGONE2);
        ull uA = fma2(fA, TWO2, NEGP2);      // 2f - 0.99999994
        ull uB = fma2(fB, TWO2, NEGP2);
        ull tA = fma2(uA, uA, NEGONE2);      // u^2 - 1 = -(1-u^2), exact negation
        ull tB = fma2(uB, uB, NEGONE2);
        float t0, t1, t2, t3;
        unpk2(tA, t0, t1); unpk2(tB, t2, t3);
        float tm = fmaxf(fmaxf(t0, t1), fmaxf(t2, t3));

        if (__builtin_expect(tm >= -6.737947e-3f, 0)) {
            // rare (~1.4%/iter): at least one lane has w >= 5 — scalar per lane
            float u0, u1, u2, u3;
            unpk2(uA, u0, u1); unpk2(uB, u2, u3);
            float uu[4] = {u0, u1, u2, u3};
            float tt[4] = {t0, t1, t2, t3};
            float cc[4];
            #pragma unroll
            for (int i = 0; i < 4; i++) {
                float l = __log2f(-tt[i]);
                float w = l * -0.69314718f;
                float pv;
                if (w < 5.0f) pv = poly_main(fmaf(l, -0.69314718f, -2.5f));
                else          pv = poly_tail(w);
                cc[i] = pv * uu[i];
            }
            sumA = add2(sumA, pk2(cc[0], cc[1]));
            sumB = add2(sumB, pk2(cc[2], cc[3]));
        } else {
            float l0 = __log2f(-t0), l1 = __log2f(-t1);
            float l2 = __log2f(-t2), l3 = __log2f(-t3);
            ull wkA = fma2(pk2(l0, l1), NEGLN2_2, M2P5_2);
            ull wkB = fma2(pk2(l2, l3), NEGLN2_2, M2P5_2);
            ull pA = fma2(P0, wkA, P1);
            ull pB = fma2(P0, wkB, P1);
            pA = fma2(pA, wkA, P2);  pB = fma2(pB, wkB, P2);
            pA = fma2(pA, wkA, P3);  pB = fma2(pB, wkB, P3);
            pA = fma2(pA, wkA, P4);  pB = fma2(pB, wkB, P4);
            pA = fma2(pA, wkA, P5);  pB = fma2(pB, wkB, P5);
            pA = fma2(pA, wkA, P6);  pB = fma2(pB, wkB, P6);
            pA = fma2(pA, wkA, P7);  pB = fma2(pB, wkB, P7);
            pA = fma2(pA, wkA, P8);  pB = fma2(pB, wkB, P8);
            sumA = fma2(pA, uA, sumA);
            sumB = fma2(pB, uB, sumB);
        }
        e = imadd(step, e, one);
    }
    float s0, s1, s2, s3;
    unpk2(sumA, s0, s1); unpk2(sumB, s2, s3);
    g_eps[gid] = ((s0 + s1) + (s2 + s3)) * (1.41421356f * 0.001f);

    __threadfence();
    __syncthreads();
    if (tid == 0) atomicAdd(&g_done[t], 1);
}

// ============================================================================
// SCAN role: 8 batch rows per block; embed folded in; waits on g_done[t];
// the designated block performs the final kld reduction + handshake reset.
// ============================================================================
__device__ void scan_role(
    int sb, bool is_reducer,
    const int* __restrict__ acts, const float* __restrict__ durs,
    const float* __restrict__ W_act, const float* __restrict__ b_act,
    const float* __restrict__ W_dur, const float* __restrict__ b_dur,
    const float* __restrict__ W_x,  const float* __restrict__ b_x,
    const float* __restrict__ W_z,  const float* __restrict__ b_z,
    const float* __restrict__ Wp1,  const float* __restrict__ bp1,
    const float* __restrict__ Wp2,  const float* __restrict__ bp2,
    const float* __restrict__ Wq1,  const float* __restrict__ bq1,
    const float* __restrict__ Wq2,  const float* __restrict__ bq2,
    const float* __restrict__ W_dec,const float* __restrict__ b_dec,
    const float* __restrict__ W_a,  const float* __restrict__ b_a,
    const float* __restrict__ W_durd,const float* __restrict__ b_durd,
    const float* __restrict__ W_ih, const float* __restrict__ W_hh,
    const float* __restrict__ b_ih, const float* __restrict__ b_hh,
    const float* __restrict__ gpost,const float* __restrict__ gprior,
    float* __restrict__ out)
{
    __shared__ float sh[Rr][Hd];
    __shared__ float sx[Rr][Hd];            // phi_x; reused as dec in epilogue
    __shared__ float s_inp[Rr][2 * Hd];     // embed input
    __shared__ int   s_act[Rr];
    __shared__ float s_dur[Rr];
    __shared__ float s_h1[Rr][NZv][Hd];
    __shared__ float s_mp[Rr][Hd];
    __shared__ float s_mq[Rr][Hd];
    __shared__ float s_z[Rr][Hd];
    __shared__ float s_pz[Rr][Hd];
    __shared__ float s_gi[Rr][3 * Hd];
    __shared__ float s_gh[Rr][3 * Hd];
    __shared__ float s_kld[Rr];

    const int tid = threadIdx.x;
    const int row0 = sb * Rr;
    float kl_acc = 0.0f;

    if (tid < Rr * Hd / 4)
        ((float4*)sh)[tid] = make_float4(0.f, 0.f, 0.f, 0.f);
    __syncthreads();

    const int rS = tid >> 5;
    const int z0 = (tid & 31) * 2;

    for (int t = 0; t < Tn; t++) {
        // S0: embed (one_hot @ W_act is a row gather) -> phi_x in sx
        if (tid < Rr) {
            s_act[tid] = acts[(row0 + tid) * Tn + t];
            s_dur[tid] = durs[(row0 + tid) * Tn + t];
        }
        __syncthreads();
        for (int idx = tid; idx < Rr * 2 * Hd; idx += 256) {
            int r = idx >> 7, c = idx & 127;
            float v;
            if (c < Hd) v = W_act[s_act[r] * Hd + c] + b_act[c];
            else        v = fmaf(s_dur[r], W_dur[c - Hd], b_dur[c - Hd]);
            s_inp[r][c] = fmaxf(v, 0.f);
        }
        __syncthreads();
        {
            float a0 = b_x[z0], a1 = b_x[z0 + 1];
            const float2* w2 = (const float2*)(W_x + z0);
            #pragma unroll 8
            for (int i = 0; i < 2 * Hd; i++) {
                float xv = s_inp[rS][i];
                float2 wv = w2[i * 32];
                a0 = fmaf(xv, wv.x, a0);
                a1 = fmaf(xv, wv.y, a1);
            }
            sx[rS][z0] = fmaxf(a0, 0.f);
            sx[rS][z0 + 1] = fmaxf(a1, 0.f);
        }
        __syncthreads();

        // S1: h1 = relu([phi_x,h] @ Wp1[n] + bp1)
        for (int u = tid; u < NZv * 16 * 4; u += 256) {
            int r2 = u / 80, rem = u % 80;
            int n = rem >> 4, o0 = (rem & 15) * 4;
            int r0 = r2 * 2;
            const float4* w4 = (const float4*)(Wp1 + (size_t)n * 128 * Hd + o0);
            float4 bb = *(const float4*)(bp1 + n * Hd + o0);
            float4 a0 = bb, a1 = bb;
            #pragma unroll 8
            for (int i = 0; i < Hd; i++) {
                float xa = sx[r0][i], xb = sx[r0 + 1][i];
                float4 wv = w4[i * 16];
                a0.x = fmaf(xa, wv.x, a0.x); a0.y = fmaf(xa, wv.y, a0.y);
                a0.z = fmaf(xa, wv.z, a0.z); a0.w = fmaf(xa, wv.w, a0.w);
                a1.x = fmaf(xb, wv.x, a1.x); a1.y = fmaf(xb, wv.y, a1.y);
                a1.z = fmaf(xb, wv.z, a1.z); a1.w = fmaf(xb, wv.w, a1.w);
            }
            #pragma unroll 8
            for (int i = 0; i < Hd; i++) {
                float xa = sh[r0][i], xb = sh[r0 + 1][i];
                float4 wv = w4[(Hd + i) * 16];
                a0.x = fmaf(xa, wv.x, a0.x); a0.y = fmaf(xa, wv.y, a0.y);
                a0.z = fmaf(xa, wv.z, a0.z); a0.w = fmaf(xa, wv.w, a0.w);
                a1.x = fmaf(xb, wv.x, a1.x); a1.y = fmaf(xb, wv.y, a1.y);
                a1.z = fmaf(xb, wv.z, a1.z); a1.w = fmaf(xb, wv.w, a1.w);
            }
            float* d0 = &s_h1[r0][n][o0];
            float* d1 = &s_h1[r0 + 1][n][o0];
            d0[0] = fmaxf(a0.x, 0.f); d0[1] = fmaxf(a0.y, 0.f); d0[2] = fmaxf(a0.z, 0.f); d0[3] = fmaxf(a0.w, 0.f);
            d1[0] = fmaxf(a1.x, 0.f); d1[1] = fmaxf(a1.y, 0.f); d1[2] = fmaxf(a1.z, 0.f); d1[3] = fmaxf(a1.w, 0.f);
        }
        __syncthreads();

        // S2: m_post
        {
            float m0 = 0.f, m1 = 0.f;
            for (int n = 0; n < NZv; n++) {
                float t0a = bp2[n * Hd + z0], t1a = bp2[n * Hd + z0 + 1];
                const float2* w2 = (const float2*)(Wp2 + (size_t)n * Hd * Hd + z0);
                #pragma unroll 8
                for (int o = 0; o < Hd; o++) {
                    float hv = s_h1[rS][n][o];
                    float2 wv = w2[o * 32];
                    t0a = fmaf(hv, wv.x, t0a);
                    t1a = fmaf(hv, wv.y, t1a);
                }
                float g = gpost[n];
                m0 = fmaf(g, t0a, m0);
                m1 = fmaf(g, t1a, m1);
            }
            s_mp[rS][z0] = m0; s_mp[rS][z0 + 1] = m1;
        }
        __syncthreads();

        // S3: prior h1 = relu(h @ Wq1[n] + bq1)
        for (int u = tid; u < NZv * 16 * 4; u += 256) {
            int r2 = u / 80, rem = u % 80;
            int n = rem >> 4, o0 = (rem & 15) * 4;
            int r0 = r2 * 2;
            const float4* w4 = (const float4*)(Wq1 + (size_t)n * Hd * Hd + o0);
            float4 bb = *(const float4*)(bq1 + n * Hd + o0);
            float4 a0 = bb, a1 = bb;
            #pragma unroll 8
            for (int i = 0; i < Hd; i++) {
                float xa = sh[r0][i], xb = sh[r0 + 1][i];
                float4 wv = w4[i * 16];
                a0.x = fmaf(xa, wv.x, a0.x); a0.y = fmaf(xa, wv.y, a0.y);
                a0.z = fmaf(xa, wv.z, a0.z); a0.w = fmaf(xa, wv.w, a0.w);
                a1.x = fmaf(xb, wv.x, a1.x); a1.y = fmaf(xb, wv.y, a1.y);
                a1.z = fmaf(xb, wv.z, a1.z); a1.w = fmaf(xb, wv.w, a1.w);
            }
            float* d0 = &s_h1[r0][n][o0];
            float* d1 = &s_h1[r0 + 1][n][o0];
            d0[0] = fmaxf(a0.x, 0.f); d0[1] = fmaxf(a0.y, 0.f); d0[2] = fmaxf(a0.z, 0.f); d0[3] = fmaxf(a0.w, 0.f);
            d1[0] = fmaxf(a1.x, 0.f); d1[1] = fmaxf(a1.y, 0.f); d1[2] = fmaxf(a1.z, 0.f); d1[3] = fmaxf(a1.w, 0.f);
        }
        __syncthreads();

        // S4: m_prior
        {
            float m0 = 0.f, m1 = 0.f;
            for (int n = 0; n < NZv; n++) {
                float t0a = bq2[n * Hd + z0], t1a = bq2[n * Hd + z0 + 1];
                const float2* w2 = (const float2*)(Wq2 + (size_t)n * Hd * Hd + z0);
                #pragma unroll 8
                for (int o = 0; o < Hd; o++) {
                    float hv = s_h1[rS][n][o];
                    float2 wv = w2[o * 32];
                    t0a = fmaf(hv, wv.x, t0a);
                    t1a = fmaf(hv, wv.y, t1a);
                }
                float g = gprior[n];
                m0 = fmaf(g, t0a, m0);
                m1 = fmaf(g, t1a, m1);
            }
            s_mq[rS][z0] = m0; s_mq[rS][z0 + 1] = m1;
        }
        __syncthreads();

        // wait for eps slice t
        if (tid == 0) {
            while (atomicAdd(&g_done[t], 0) < EPS_T_BLOCKS) __nanosleep(200);
            __threadfence();
        }
        __syncthreads();

        // S5: KL + z
        {
            const float* ep = g_eps + ((size_t)t * Bn + row0 + rS) * Hd + z0;
            #pragma unroll
            for (int q = 0; q < 2; q++) {
                float mp = s_mp[rS][z0 + q], mq = s_mq[rS][z0 + q];
                float pm = fmaxf(mp, 0.0f), qm = fmaxf(mq, 0.0f);
                float ps = softplusf(mp),   qs = softplusf(mq);
                float d = pm - qm;
                kl_acc += logf(qs / ps) + (ps * ps + d * d) / (2.0f * qs * qs) - 0.5f;
                s_z[rS][z0 + q] = fmaf(ps, ep[q], pm);
            }
        }
        __syncthreads();

        // S6: phi_z
        {
            float a0 = b_z[z0], a1 = b_z[z0 + 1];
            const float2* w2 = (const float2*)(W_z + z0);
            #pragma unroll 8
            for (int i = 0; i < Hd; i++) {
                float xv = s_z[rS][i];
                float2 wv = w2[i * 32];
                a0 = fmaf(xv, wv.x, a0);
                a1 = fmaf(xv, wv.y, a1);
            }
            s_pz[rS][z0] = fmaxf(a0, 0.f);
            s_pz[rS][z0 + 1] = fmaxf(a1, 0.f);
        }
        __syncthreads();

        // S7: GRU gates
        for (int u = tid; u < 384; u += 256) {
            if (u < 192) {
                int r2 = u / 48, k0i = (u % 48) * 4;
                int r0 = r2 * 2;
                const float4* w4 = (const float4*)(W_ih + k0i);
                float4 bb = *(const float4*)(b_ih + k0i);
                float4 a0 = bb, a1 = bb;
                #pragma unroll 8
                for (int i = 0; i < Hd; i++) {
                    float xa = sx[r0][i], xb = sx[r0 + 1][i];
                    float4 wv = w4[i * 48];
                    a0.x = fmaf(xa, wv.x, a0.x); a0.y = fmaf(xa, wv.y, a0.y);
                    a0.z = fmaf(xa, wv.z, a0.z); a0.w = fmaf(xa, wv.w, a0.w);
                    a1.x = fmaf(xb, wv.x, a1.x); a1.y = fmaf(xb, wv.y, a1.y);
                    a1.z = fmaf(xb, wv.z, a1.z); a1.w = fmaf(xb, wv.w, a1.w);
                }
                #pragma unroll 8
                for (int i = 0; i < Hd; i++) {
                    float xa = s_pz[r0][i], xb = s_pz[r0 + 1][i];
                    float4 wv = w4[(Hd + i) * 48];
                    a0.x = fmaf(xa, wv.x, a0.x); a0.y = fmaf(xa, wv.y, a0.y);
                    a0.z = fmaf(xa, wv.z, a0.z); a0.w = fmaf(xa, wv.w, a0.w);
                    a1.x = fmaf(xb, wv.x, a1.x); a1.y = fmaf(xb, wv.y, a1.y);
                    a1.z = fmaf(xb, wv.z, a1.z); a1.w = fmaf(xb, wv.w, a1.w);
                }
                *(float4*)&s_gi[r0][k0i] = a0;
                *(float4*)&s_gi[r0 + 1][k0i] = a1;
            } else {
                int gu = u - 192;
                int r2 = gu / 48, k0i = (gu % 48) * 4;
                int r0 = r2 * 2;
                const float4* w4 = (const float4*)(W_hh + k0i);
                float4 bb = *(const float4*)(b_hh + k0i);
                float4 a0 = bb, a1 = bb;
                #pragma unroll 8
                for (int i = 0; i < Hd; i++) {
                    float xa = sh[r0][i], xb = sh[r0 + 1][i];
                    float4 wv = w4[i * 48];
                    a0.x = fmaf(xa, wv.x, a0.x); a0.y = fmaf(xa, wv.y, a0.y);
                    a0.z = fmaf(xa, wv.z, a0.z); a0.w = fmaf(xa, wv.w, a0.w);
                    a1.x = fmaf(xb, wv.x, a1.x); a1.y = fmaf(xb, wv.y, a1.y);
                    a1.z = fmaf(xb, wv.z, a1.z); a1.w = fmaf(xb, wv.w, a1.w);
                }
                *(float4*)&s_gh[r0][k0i] = a0;
                *(float4*)&s_gh[r0 + 1][k0i] = a1;
            }
        }
        __syncthreads();

        // S8: h update
        for (int idx = tid; idx < Rr * Hd; idx += 256) {
            int r = idx >> 6, j = idx & 63;
            float ir = s_gi[r][j], iz = s_gi[r][Hd + j], in_ = s_gi[r][2 * Hd + j];
            float hr = s_gh[r][j], hz = s_gh[r][Hd + j], hn  = s_gh[r][2 * Hd + j];
            float rg = sigmoidf(ir + hr);
            float zz = sigmoidf(iz + hz);
            float nn = tanhf(fmaf(rg, hn, in_));
            sh[r][j] = (1.0f - zz) * nn + zz * sh[r][j];
        }
        __syncthreads();
    }

    // reduce per-thread KL
    #pragma unroll
    for (int off = 16; off; off >>= 1)
        kl_acc += __shfl_xor_sync(0xFFFFFFFFu, kl_acc, off);
    if ((tid & 31) == 0) s_kld[rS] = kl_acc;
    __syncthreads();

    // ---------- epilogue ----------
    for (int u = tid; u < NZv * 16 * 4; u += 256) {
        int r2 = u / 80, rem = u % 80;
        int n = rem >> 4, o0 = (rem & 15) * 4;
        int r0 = r2 * 2;
        const float4* w4 = (const float4*)(Wq1 + (size_t)n * Hd * Hd + o0);
        float4 bb = *(const float4*)(bq1 + n * Hd + o0);
        float4 a0 = bb, a1 = bb;
        #pragma unroll 8
        for (int i = 0; i < Hd; i++) {
            float xa = sh[r0][i], xb = sh[r0 + 1][i];
            float4 wv = w4[i * 16];
            a0.x = fmaf(xa, wv.x, a0.x); a0.y = fmaf(xa, wv.y, a0.y);
            a0.z = fmaf(xa, wv.z, a0.z); a0.w = fmaf(xa, wv.w, a0.w);
            a1.x = fmaf(xb, wv.x, a1.x); a1.y = fmaf(xb, wv.y, a1.y);
            a1.z = fmaf(xb, wv.z, a1.z); a1.w = fmaf(xb, wv.w, a1.w);
        }
        float* d0 = &s_h1[r0][n][o0];
        float* d1 = &s_h1[r0 + 1][n][o0];
        d0[0] = fmaxf(a0.x, 0.f); d0[1] = fmaxf(a0.y, 0.f); d0[2] = fmaxf(a0.z, 0.f); d0[3] = fmaxf(a0.w, 0.f);
        d1[0] = fmaxf(a1.x, 0.f); d1[1] = fmaxf(a1.y, 0.f); d1[2] = fmaxf(a1.z, 0.f); d1[3] = fmaxf(a1.w, 0.f);
    }
    if (tid == 0) {
        while (atomicAdd(&g_done[Tn], 0) < EPS_T_BLOCKS) __nanosleep(200);
        __threadfence();
    }
    __syncthreads();
    {
        float m0 = 0.f, m1 = 0.f;
        for (int n = 0; n < NZv; n++) {
            float t0a = bq2[n * Hd + z0], t1a = bq2[n * Hd + z0 + 1];
            const float2* w2 = (const float2*)(Wq2 + (size_t)n * Hd * Hd + z0);
            #pragma unroll 8
            for (int o = 0; o < Hd; o++) {
                float hv = s_h1[rS][n][o];
                float2 wv = w2[o * 32];
                t0a = fmaf(hv, wv.x, t0a);
                t1a = fmaf(hv, wv.y, t1a);
            }
            float g = gprior[n];
            m0 = fmaf(g, t0a, m0);
            m1 = fmaf(g, t1a, m1);
        }
        const float* ep = g_eps + ((size_t)Tn * Bn + row0 + rS) * Hd + z0;
        s_z[rS][z0]     = fmaf(softplusf(m0), ep[0], fmaxf(m0, 0.f));
        s_z[rS][z0 + 1] = fmaf(softplusf(m1), ep[1], fmaxf(m1, 0.f));
    }
    __syncthreads();
    {
        float a0 = b_z[z0], a1 = b_z[z0 + 1];
        const float2* w2 = (const float2*)(W_z + z0);
        #pragma unroll 8
        for (int i = 0; i < Hd; i++) {
            float xv = s_z[rS][i];
            float2 wv = w2[i * 32];
            a0 = fmaf(xv, wv.x, a0);
            a1 = fmaf(xv, wv.y, a1);
        }
        s_pz[rS][z0] = fmaxf(a0, 0.f);
        s_pz[rS][z0 + 1] = fmaxf(a1, 0.f);
    }
    __syncthreads();
    {
        float a0 = b_dec[z0], a1 = b_dec[z0 + 1];
        const float2* w2 = (const float2*)(W_dec + z0);
        #pragma unroll 8
        for (int i = 0; i < Hd; i++) {
            float xv = s_pz[rS][i];
            float2 wv = w2[i * 32];
            a0 = fmaf(xv, wv.x, a0);
            a1 = fmaf(xv, wv.y, a1);
        }
        #pragma unroll 8
        for (int i = 0; i < Hd; i++) {
            float xv = sh[rS][i];
            float2 wv = w2[(Hd + i) * 32];
            a0 = fmaf(xv, wv.x, a0);
            a1 = fmaf(xv, wv.y, a1);
        }
        sx[rS][z0] = fmaxf(a0, 0.f);
        sx[rS][z0 + 1] = fmaxf(a1, 0.f);
    }
    __syncthreads();
    if (tid < Rr * ACTD) {
        int r = tid / ACTD, a = tid % ACTD;
        float acc = b_a[a];
        #pragma unroll 8
        for (int j = 0; j < Hd; j++) acc = fmaf(sx[r][j], W_a[j * ACTD + a], acc);
        s_gi[r][a] = acc;
        out[(size_t)(row0 + r) * ACTD + a] = acc;
    }
    __syncthreads();
    {
        float a0 = b_act[z0], a1 = b_act[z0 + 1];
        const float2* w2 = (const float2*)(W_act + z0);
        #pragma unroll
        for (int a = 0; a < ACTD; a++) {
            float xv = s_gi[rS][a];
            float2 wv = w2[a * 32];
            a0 = fmaf(xv, wv.x, a0);
            a1 = fmaf(xv, wv.y, a1);
        }
        s_mp[rS][z0] = fmaxf(a0, 0.f);
        s_mp[rS][z0 + 1] = fmaxf(a1, 0.f);
    }
    __syncthreads();
    if (tid < Rr) {
        int r = tid;
        float acc = b_durd[0];
        #pragma unroll 8
        for (int j = 0; j < Hd; j++) acc = fmaf(s_mp[r][j], W_durd[j], acc);
        #pragma unroll 8
        for (int j = 0; j < Hd; j++) acc = fmaf(sx[r][j],  W_durd[Hd + j], acc);
        out[(size_t)Bn * ACTD + row0 + r] = acc;
        out[(size_t)Bn * ACTD + Bn + row0 + r] = softplusf(acc);
        g_kld[row0 + r] = s_kld[r];
    }

    // ---------- finalization: all scan blocks signal; reducer block sums kld ----------
    __threadfence();
    __syncthreads();
    if (tid == 0) atomicAdd(&g_scan_done, 1);

    if (is_reducer) {
        __shared__ float rs[256];
        if (tid == 0) {
            while (atomicAdd(&g_scan_done, 0) < SCAN_BLOCKS) __nanosleep(200);
            __threadfence();
        }
        __syncthreads();
        rs[tid] = g_kld[tid] + g_kld[tid + 256] + g_kld[tid + 512] + g_kld[tid + 768];
        __syncthreads();
        for (int st = 128; st > 0; st >>= 1) {
            if (tid < st) rs[tid] += rs[tid + st];
            __syncthreads();
        }
        if (tid == 0) out[(size_t)Bn * ACTD + 2 * Bn] = rs[0] * (1.0f / Bn);
        // reset handshakes for the next (graph-replayed) invocation
        if (tid <= Tn) g_done[tid] = 0;
        if (tid == 0) g_scan_done = 0;
    }
}

// ============================================================================
// fused kernel (the ONLY launch):
//   blocks [0, EPS_TOTAL)                 = eps  (fill the machine first)
//   blocks [EPS_TOTAL, EPS_TOTAL+128)     = scan (last wave; eps gets full chip)
// Dependency is one-directional (scan waits on eps) -> no deadlock.
// ============================================================================
__global__ void __launch_bounds__(256) fused_kernel(
    const int* __restrict__ acts, const float* __restrict__ durs,
    const float* __restrict__ W_act, const float* __restrict__ b_act,
    const float* __restrict__ W_dur, const float* __restrict__ b_dur,
    const float* __restrict__ W_x,  const float* __restrict__ b_x,
    const float* __restrict__ W_z,  const float* __restrict__ b_z,
    const float* __restrict__ Wp1,  const float* __restrict__ bp1,
    const float* __restrict__ Wp2,  const float* __restrict__ bp2,
    const float* __restrict__ Wq1,  const float* __restrict__ bq1,
    const float* __restrict__ Wq2,  const float* __restrict__ bq2,
    const float* __restrict__ W_dec,const float* __restrict__ b_dec,
    const float* __restrict__ W_a,  const float* __restrict__ b_a,
    const float* __restrict__ W_durd,const float* __restrict__ b_durd,
    const float* __restrict__ W_ih, const float* __restrict__ W_hh,
    const float* __restrict__ b_ih, const float* __restrict__ b_hh,
    const float* __restrict__ gpost,const float* __restrict__ gprior,
    float* __restrict__ out)
{
    if (blockIdx.x < EPS_TOTAL) {
        eps_role(blockIdx.x);
    } else {
        int sb = blockIdx.x - EPS_TOTAL;
        scan_role(sb, sb == 0,
                  acts, durs, W_act, b_act, W_dur, b_dur, W_x, b_x, W_z, b_z,
                  Wp1, bp1, Wp2, bp2, Wq1, bq1, Wq2, bq2, W_dec, b_dec,
                  W_a, b_a, W_durd, b_durd, W_ih, W_hh, b_ih, b_hh,
                  gpost, gprior, out);
    }
}

// ---------------- launch ----------------
extern "C" void kernel_launch(void* const* d_in, const int* in_sizes, int n_in,
                              void* d_out, int out_size) {
    const int*   acts   = (const int*)  d_in[0];
    const float* durs   = (const float*)d_in[1];
    const float* W_act  = (const float*)d_in[2];
    const float* b_act  = (const float*)d_in[3];
    const float* W_dur  = (const float*)d_in[4];
    const float* b_dur  = (const float*)d_in[5];
    const float* W_x    = (const float*)d_in[6];
    const float* b_x    = (const float*)d_in[7];
    const float* W_z    = (const float*)d_in[8];
    const float* b_z    = (const float*)d_in[9];
    const float* Wp1    = (const float*)d_in[10];
    const float* bp1    = (const float*)d_in[11];
    const float* Wp2    = (const float*)d_in[12];
    const float* bp2    = (const float*)d_in[13];
    const float* Wq1    = (const float*)d_in[14];
    const float* bq1    = (const float*)d_in[15];
    const float* Wq2    = (const float*)d_in[16];
    const float* bq2    = (const float*)d_in[17];
    const float* W_dec  = (const float*)d_in[18];
    const float* b_dec  = (const float*)d_in[19];
    const float* W_a    = (const float*)d_in[20];
    const float* b_a    = (const float*)d_in[21];
    const float* W_durd = (const float*)d_in[22];
    const float* b_durd = (const float*)d_in[23];
    const float* W_ih   = (const float*)d_in[24];
    const float* W_hh   = (const float*)d_in[25];
    const float* b_ih   = (const float*)d_in[26];
    const float* b_hh   = (const float*)d_in[27];
    const float* gpost  = (const float*)d_in[28];
    const float* gprior = (const float*)d_in[29];
    float* out = (float*)d_out;

    fused_kernel<<<EPS_TOTAL + SCAN_BLOCKS, 256>>>(
        acts, durs, W_act, b_act, W_dur, b_dur, W_x, b_x, W_z, b_z,
        Wp1, bp1, Wp2, bp2, Wq1, bq1, Wq2, bq2, W_dec, b_dec,
        W_a, b_a, W_durd, b_durd, W_ih, W_hh, b_ih, b_hh,
        gpost, gprior, out);
}

// round 11
// speedup vs baseline: 1.1316x; 1.1316x over previous
#include <cuda_runtime.h>

#define Bn 1024
#define Tn 128
#define Hd 64
#define NZv 5
#define ACTD 20
#define Rr 16
#define SCAN_BLOCKS 64
#define EPS_T_BLOCKS 256                     // 256 blocks x 256 threads = 65536 outputs per timestep
#define EPS_TOTAL ((Tn + 1) * EPS_T_BLOCKS)  // 33024 eps blocks

typedef unsigned long long ull;

// ---------------- device scratch (static allocation only) ----------------
__device__ float g_eps[(size_t)(Tn + 1) * Bn * Hd];     // (T+1,B,H)
__device__ float g_kld[Bn];
__device__ int   g_done[Tn + 1];                        // zero-init at load; reset by reducer
__device__ int   g_scan_done;                           // ditto
__device__ unsigned g_one = 1;   // runtime-opaque 1: forces adds onto IMAD (fma pipe)

// ---------------- f32x2 packed helpers ----------------
__device__ __forceinline__ ull pk2(float lo, float hi) {
    ull r; asm("mov.b64 %0, {%1, %2};" : "=l"(r) : "f"(lo), "f"(hi)); return r;
}
__device__ __forceinline__ void unpk2(ull v, float& lo, float& hi) {
    asm("mov.b64 {%0, %1}, %2;" : "=f"(lo), "=f"(hi) : "l"(v));
}
__device__ __forceinline__ ull pki2(unsigned lo, unsigned hi) {
    ull r; asm("mov.b64 %0, {%1, %2};" : "=l"(r) : "r"(lo), "r"(hi)); return r;
}
__device__ __forceinline__ ull fma2(ull a, ull b, ull c) {
    ull d; asm("fma.rn.f32x2 %0, %1, %2, %3;" : "=l"(d) : "l"(a), "l"(b), "l"(c)); return d;
}
__device__ __forceinline__ ull add2(ull a, ull b) {
    ull d; asm("add.rn.f32x2 %0, %1, %2;" : "=l"(d) : "l"(a), "l"(b)); return d;
}
__device__ __forceinline__ ull dup2(float x) { return pk2(x, x); }

// ---------------- math helpers ----------------
__device__ __forceinline__ float softplusf(float x) {
    return fmaxf(x, 0.0f) + log1pf(expf(-fabsf(x)));
}
__device__ __forceinline__ float sigmoidf(float x) {
    return 1.0f / (1.0f + expf(-x));
}
__device__ __forceinline__ unsigned imadd(unsigned a, unsigned b, unsigned one) {
    unsigned d;
    asm("mad.lo.u32 %0, %1, %2, %3;" : "=r"(d) : "r"(a), "r"(one), "r"(b));
    return d;
}
__device__ __forceinline__ float poly_main(float wk) {
    float p = 2.81022636e-08f;
    p = fmaf(p, wk, 3.43273939e-07f);
    p = fmaf(p, wk, -3.5233877e-06f);
    p = fmaf(p, wk, -4.39150654e-06f);
    p = fmaf(p, wk, 0.00021858087f);
    p = fmaf(p, wk, -0.00125372503f);
    p = fmaf(p, wk, -0.00417768164f);
    p = fmaf(p, wk, 0.246640727f);
    p = fmaf(p, wk, 1.50140941f);
    return p;
}
__device__ __forceinline__ float poly_tail(float w) {
    float ws = sqrtf(w) - 3.0f;
    float p = -0.000200214257f;
    p = fmaf(p, ws, 0.000100950558f);
    p = fmaf(p, ws, 0.00134934322f);
    p = fmaf(p, ws, -0.00367342844f);
    p = fmaf(p, ws, 0.00573950773f);
    p = fmaf(p, ws, -0.0076224613f);
    p = fmaf(p, ws, 0.00943887047f);
    p = fmaf(p, ws, 1.00167406f);
    p = fmaf(p, ws, 2.83297682f);
    return p;
}

// general threefry (prologue key fold only)
__device__ __forceinline__ uint2 threefry2x32(unsigned k0, unsigned k1,
                                              unsigned x0, unsigned x1) {
    unsigned ks2 = k0 ^ k1 ^ 0x1BD11BDAu;
#define TF_RND(r) { x0 += x1; x1 = __funnelshift_l(x1, x1, r); x1 ^= x0; }
    x0 += k0; x1 += k1;
    TF_RND(13) TF_RND(15) TF_RND(26) TF_RND(6)
    x0 += k1;  x1 += ks2 + 1u;
    TF_RND(17) TF_RND(29) TF_RND(16) TF_RND(24)
    x0 += ks2; x1 += k0 + 2u;
    TF_RND(13) TF_RND(15) TF_RND(26) TF_RND(6)
    x0 += k0;  x1 += k1 + 3u;
    TF_RND(17) TF_RND(29) TF_RND(16) TF_RND(24)
    x0 += k1;  x1 += ks2 + 4u;
    TF_RND(13) TF_RND(15) TF_RND(26) TF_RND(6)
    x0 += ks2; x1 += k0 + 5u;
#undef TF_RND
    uint2 r; r.x = x0; r.y = x1; return r;
}

// hot path: counter word0 == 0, adds on fma pipe; returns y0 ^ y1
__device__ __forceinline__ unsigned tf_xor(
    unsigned k0, unsigned k1, unsigned ks2,
    unsigned c1, unsigned c2, unsigned c3, unsigned c4, unsigned c5,
    unsigned e, unsigned k1d, unsigned one)
{
    unsigned x0 = k0;
    unsigned x1 = imadd(e, k1d, one);
#define TF_RND(r) { x0 = imadd(x1, x0, one); x1 = __funnelshift_l(x1, x1, r); x1 ^= x0; }
    TF_RND(13) TF_RND(15) TF_RND(26) TF_RND(6)
    x0 = imadd(k1, x0, one);  x1 = imadd(c1, x1, one);
    TF_RND(17) TF_RND(29) TF_RND(16) TF_RND(24)
    x0 = imadd(ks2, x0, one); x1 = imadd(c2, x1, one);
    TF_RND(13) TF_RND(15) TF_RND(26) TF_RND(6)
    x0 = imadd(k0, x0, one);  x1 = imadd(c3, x1, one);
    TF_RND(17) TF_RND(29) TF_RND(16) TF_RND(24)
    x0 = imadd(k1, x0, one);  x1 = imadd(c4, x1, one);
    TF_RND(13) TF_RND(15) TF_RND(26) TF_RND(6)
    x0 = imadd(ks2, x0, one); x1 = imadd(c5, x1, one);
#undef TF_RND
    return x0 ^ x1;
}

// mantissa word via funnel shift: (bits>>9) | 0x3F800000 in ONE SHF
__device__ __forceinline__ unsigned mant(unsigned bits) {
    return __funnelshift_r(bits, 0x7Fu, 9);
}

// ============================================================================
// EPS role (unchanged from R9)
// ============================================================================
__device__ __noinline__ void eps_role(int eb) {
    const int tid = threadIdx.x;
    const int t = eb >> 8;
    const unsigned bz = (unsigned)((eb & 255) * 256 + tid);
    const int gid = t * (Bn * Hd) + (int)bz;

    const unsigned one = g_one;
    uint2 kk = threefry2x32(0u, 42u, 0u, (unsigned)t);
    const unsigned k0 = kk.x, k1 = kk.y;
    const unsigned ks2 = k0 ^ k1 ^ 0x1BD11BDAu;
    const unsigned c1 = ks2 + 1u, c2 = k0 + 2u, c3 = k1 + 3u,
                   c4 = ks2 + 4u, c5 = k0 + 5u;
    const unsigned k1d0 = k1, k1d1 = k1 + 65536u,
                   k1d2 = k1 + 131072u, k1d3 = k1 + 196608u;

    const ull NEGONE2  = dup2(-1.0f);
    const ull TWO2     = dup2(2.0f);
    const ull NEGP2    = dup2(-0.99999994f);
    const ull NEGLN2_2 = dup2(-0.69314718f);
    const ull M2P5_2   = dup2(-2.5f);
    const ull P0 = dup2(2.81022636e-08f);
    const ull P1 = dup2(3.43273939e-07f);
    const ull P2 = dup2(-3.5233877e-06f);
    const ull P3 = dup2(-4.39150654e-06f);
    const ull P4 = dup2(0.00021858087f);
    const ull P5 = dup2(-0.00125372503f);
    const ull P6 = dup2(-0.00417768164f);
    const ull P7 = dup2(0.246640727f);
    const ull P8 = dup2(1.50140941f);

    ull sumA = 0ull, sumB = 0ull;
    unsigned e = bz;
    const unsigned step = 262144u;

    #pragma unroll 2
    for (int s = 0; s < 250; s++) {
        unsigned b0 = tf_xor(k0, k1, ks2, c1, c2, c3, c4, c5, e, k1d0, one);
        unsigned b1 = tf_xor(k0, k1, ks2, c1, c2, c3, c4, c5, e, k1d1, one);
        unsigned b2 = tf_xor(k0, k1, ks2, c1, c2, c3, c4, c5, e, k1d2, one);
        unsigned b3 = tf_xor(k0, k1, ks2, c1, c2, c3, c4, c5, e, k1d3, one);

        ull gA = pki2(mant(b0), mant(b1));
        ull gB = pki2(mant(b2), mant(b3));
        ull fA = add2(gA, NEGONE2);
        ull fB = add2(gB, NEGONE2);
        ull uA = fma2(fA, TWO2, NEGP2);
        ull uB = fma2(fB, TWO2, NEGP2);
        ull tA = fma2(uA, uA, NEGONE2);
        ull tB = fma2(uB, uB, NEGONE2);
        float t0, t1, t2, t3;
        unpk2(tA, t0, t1); unpk2(tB, t2, t3);
        float tm = fmaxf(fmaxf(t0, t1), fmaxf(t2, t3));

        if (__builtin_expect(tm >= -6.737947e-3f, 0)) {
            float u0, u1, u2, u3;
            unpk2(uA, u0, u1); unpk2(uB, u2, u3);
            float uu[4] = {u0, u1, u2, u3};
            float tt[4] = {t0, t1, t2, t3};
            float cc[4];
            #pragma unroll
            for (int i = 0; i < 4; i++) {
                float l = __log2f(-tt[i]);
                float w = l * -0.69314718f;
                float pv;
                if (w < 5.0f) pv = poly_main(fmaf(l, -0.69314718f, -2.5f));
                else          pv = poly_tail(w);
                cc[i] = pv * uu[i];
            }
            sumA = add2(sumA, pk2(cc[0], cc[1]));
            sumB = add2(sumB, pk2(cc[2], cc[3]));
        } else {
            float l0 = __log2f(-t0), l1 = __log2f(-t1);
            float l2 = __log2f(-t2), l3 = __log2f(-t3);
            ull wkA = fma2(pk2(l0, l1), NEGLN2_2, M2P5_2);
            ull wkB = fma2(pk2(l2, l3), NEGLN2_2, M2P5_2);
            ull pA = fma2(P0, wkA, P1);
            ull pB = fma2(P0, wkB, P1);
            pA = fma2(pA, wkA, P2);  pB = fma2(pB, wkB, P2);
            pA = fma2(pA, wkA, P3);  pB = fma2(pB, wkB, P3);
            pA = fma2(pA, wkA, P4);  pB = fma2(pB, wkB, P4);
            pA = fma2(pA, wkA, P5);  pB = fma2(pB, wkB, P5);
            pA = fma2(pA, wkA, P6);  pB = fma2(pB, wkB, P6);
            pA = fma2(pA, wkA, P7);  pB = fma2(pB, wkB, P7);
            pA = fma2(pA, wkA, P8);  pB = fma2(pB, wkB, P8);
            sumA = fma2(pA, uA, sumA);
            sumB = fma2(pB, uB, sumB);
        }
        e = imadd(step, e, one);
    }
    float s0, s1, s2, s3;
    unpk2(sumA, s0, s1); unpk2(sumB, s2, s3);
    g_eps[gid] = ((s0 + s1) + (s2 + s3)) * (1.41421356f * 0.001f);

    __threadfence();
    __syncthreads();
    if (tid == 0) atomicAdd(&g_done[t], 1);
}

// ============================================================================
// SCAN role: 16 batch rows per block (64 blocks); prior-first, register m_prior
// ============================================================================
__device__ void scan_role(
    int sb,
    const int* __restrict__ acts, const float* __restrict__ durs,
    const float* __restrict__ W_act, const float* __restrict__ b_act,
    const float* __restrict__ W_dur, const float* __restrict__ b_dur,
    const float* __restrict__ W_x,  const float* __restrict__ b_x,
    const float* __restrict__ W_z,  const float* __restrict__ b_z,
    const float* __restrict__ Wp1,  const float* __restrict__ bp1,
    const float* __restrict__ Wp2,  const float* __restrict__ bp2,
    const float* __restrict__ Wq1,  const float* __restrict__ bq1,
    const float* __restrict__ Wq2,  const float* __restrict__ bq2,
    const float* __restrict__ W_dec,const float* __restrict__ b_dec,
    const float* __restrict__ W_a,  const float* __restrict__ b_a,
    const float* __restrict__ W_durd,const float* __restrict__ b_durd,
    const float* __restrict__ W_ih, const float* __restrict__ W_hh,
    const float* __restrict__ b_ih, const float* __restrict__ b_hh,
    const float* __restrict__ gpost,const float* __restrict__ gprior,
    float* __restrict__ out)
{
    __shared__ float sh[Rr][Hd];                // h state              4KB
    __shared__ float sx[Rr][Hd];                // phi_x / dec          4KB
    __shared__ float u_buf[Rr][2 * Hd];         // inp | (z, pz)        8KB
    __shared__ float u_big[Rr * NZv * Hd];      // h1 | (gi, gh 8 rows) 20KB
    __shared__ float s_logit[Rr][ACTD];         //                      1.25KB

#define S_INP(r,c) u_buf[r][c]
#define S_Z(r,j)   u_buf[r][j]
#define S_PZ(r,j)  u_buf[r][Hd + (j)]
#define S_H1(r,n,o) u_big[(((r) * NZv) + (n)) * Hd + (o)]
#define S_GI(lr,k) u_big[(lr) * 192 + (k)]
#define S_GH(lr,k) u_big[1536 + (lr) * 192 + (k)]

    const int tid = threadIdx.x;
    const int row0 = sb * Rr;
    const int rT = tid >> 4;            // 0..15
    const int c0 = (tid & 15) * 4;      // 0..60 step 4
    // 2-row mapping for mixture-mean stages (threads 0..127 active)
    const int rA = (tid >> 4) * 2;      // 0..14 even
    const int cc = (tid & 15) * 4;

    float klA = 0.f, klB = 0.f;
    float mqA0=0,mqA1=0,mqA2=0,mqA3=0, mqB0=0,mqB1=0,mqB2=0,mqB3=0;

    for (int idx = tid; idx < Rr * Hd; idx += 256) sh[idx >> 6][idx & 63] = 0.f;
    __syncthreads();

    for (int t = 0; t < Tn; t++) {
        // ---- S0: embed input ----
        for (int idx = tid; idx < Rr * 2 * Hd; idx += 256) {
            int r = idx >> 7, c = idx & 127;
            float v;
            if (c < Hd) {
                int a = acts[(row0 + r) * Tn + t];
                v = W_act[a * Hd + c] + b_act[c];
            } else {
                float du = durs[(row0 + r) * Tn + t];
                v = fmaf(du, W_dur[c - Hd], b_dur[c - Hd]);
            }
            S_INP(r, c) = fmaxf(v, 0.f);
        }
        __syncthreads();

        // ---- phi_x: (rT, c0), 128-dot ----
        {
            float4 a = *(const float4*)(b_x + c0);
            const float4* w4 = (const float4*)(W_x + c0);
            #pragma unroll 8
            for (int i = 0; i < 2 * Hd; i++) {
                float xv = S_INP(rT, i);
                float4 wv = w4[i * 16];
                a.x = fmaf(xv, wv.x, a.x); a.y = fmaf(xv, wv.y, a.y);
                a.z = fmaf(xv, wv.z, a.z); a.w = fmaf(xv, wv.w, a.w);
            }
            sx[rT][c0]   = fmaxf(a.x, 0.f); sx[rT][c0+1] = fmaxf(a.y, 0.f);
            sx[rT][c0+2] = fmaxf(a.z, 0.f); sx[rT][c0+3] = fmaxf(a.w, 0.f);
        }
        __syncthreads();

        // ---- S3': prior h1 = relu(h @ Wq1 + bq1), 4-row tiled ----
        for (int u = tid; u < 4 * NZv * 16; u += 256) {
            int rg = u / 80, rem = u % 80;
            int n = rem >> 4, o0 = (rem & 15) * 4;
            int r0 = rg * 4;
            const float4* w4 = (const float4*)(Wq1 + (size_t)n * 4096 + o0);
            float4 bb = *(const float4*)(bq1 + n * Hd + o0);
            float4 a0 = bb, a1 = bb, a2 = bb, a3 = bb;
            #pragma unroll 8
            for (int i = 0; i < Hd; i++) {
                float4 wv = w4[i * 16];
                float x0 = sh[r0][i], x1 = sh[r0+1][i], x2 = sh[r0+2][i], x3 = sh[r0+3][i];
                a0.x=fmaf(x0,wv.x,a0.x); a0.y=fmaf(x0,wv.y,a0.y); a0.z=fmaf(x0,wv.z,a0.z); a0.w=fmaf(x0,wv.w,a0.w);
                a1.x=fmaf(x1,wv.x,a1.x); a1.y=fmaf(x1,wv.y,a1.y); a1.z=fmaf(x1,wv.z,a1.z); a1.w=fmaf(x1,wv.w,a1.w);
                a2.x=fmaf(x2,wv.x,a2.x); a2.y=fmaf(x2,wv.y,a2.y); a2.z=fmaf(x2,wv.z,a2.z); a2.w=fmaf(x2,wv.w,a2.w);
                a3.x=fmaf(x3,wv.x,a3.x); a3.y=fmaf(x3,wv.y,a3.y); a3.z=fmaf(x3,wv.z,a3.z); a3.w=fmaf(x3,wv.w,a3.w);
            }
            float* d0 = &S_H1(r0, n, o0);   float* d1 = &S_H1(r0+1, n, o0);
            float* d2 = &S_H1(r0+2, n, o0); float* d3 = &S_H1(r0+3, n, o0);
            d0[0]=fmaxf(a0.x,0.f); d0[1]=fmaxf(a0.y,0.f); d0[2]=fmaxf(a0.z,0.f); d0[3]=fmaxf(a0.w,0.f);
            d1[0]=fmaxf(a1.x,0.f); d1[1]=fmaxf(a1.y,0.f); d1[2]=fmaxf(a1.z,0.f); d1[3]=fmaxf(a1.w,0.f);
            d2[0]=fmaxf(a2.x,0.f); d2[1]=fmaxf(a2.y,0.f); d2[2]=fmaxf(a2.z,0.f); d2[3]=fmaxf(a2.w,0.f);
            d3[0]=fmaxf(a3.x,0.f); d3[1]=fmaxf(a3.y,0.f); d3[2]=fmaxf(a3.z,0.f); d3[3]=fmaxf(a3.w,0.f);
        }
        __syncthreads();

        // ---- S4': m_prior -> registers (threads 0..127, 2 rows each) ----
        if (tid < 128) {
            mqA0=0;mqA1=0;mqA2=0;mqA3=0; mqB0=0;mqB1=0;mqB2=0;mqB3=0;
            for (int n = 0; n < NZv; n++) {
                float4 bb = *(const float4*)(bq2 + n * Hd + cc);
                float4 aA = bb, aB = bb;
                const float4* w4 = (const float4*)(Wq2 + (size_t)n * 4096 + cc);
                #pragma unroll 8
                for (int o = 0; o < Hd; o++) {
                    float4 wv = w4[o * 16];
                    float hA = S_H1(rA, n, o), hB = S_H1(rA+1, n, o);
                    aA.x=fmaf(hA,wv.x,aA.x); aA.y=fmaf(hA,wv.y,aA.y); aA.z=fmaf(hA,wv.z,aA.z); aA.w=fmaf(hA,wv.w,aA.w);
                    aB.x=fmaf(hB,wv.x,aB.x); aB.y=fmaf(hB,wv.y,aB.y); aB.z=fmaf(hB,wv.z,aB.z); aB.w=fmaf(hB,wv.w,aB.w);
                }
                float g = gprior[n];
                mqA0=fmaf(g,aA.x,mqA0); mqA1=fmaf(g,aA.y,mqA1); mqA2=fmaf(g,aA.z,mqA2); mqA3=fmaf(g,aA.w,mqA3);
                mqB0=fmaf(g,aB.x,mqB0); mqB1=fmaf(g,aB.y,mqB1); mqB2=fmaf(g,aB.z,mqB2); mqB3=fmaf(g,aB.w,mqB3);
            }
        }
        __syncthreads();

        // ---- S1: post h1 = relu([phi_x,h] @ Wp1 + bp1), 4-row tiled ----
        for (int u = tid; u < 4 * NZv * 16; u += 256) {
            int rg = u / 80, rem = u % 80;
            int n = rem >> 4, o0 = (rem & 15) * 4;
            int r0 = rg * 4;
            const float4* w4 = (const float4*)(Wp1 + (size_t)n * 8192 + o0);
            float4 bb = *(const float4*)(bp1 + n * Hd + o0);
            float4 a0 = bb, a1 = bb, a2 = bb, a3 = bb;
            #pragma unroll 8
            for (int i = 0; i < Hd; i++) {
                float4 wv = w4[i * 16];
                float x0 = sx[r0][i], x1 = sx[r0+1][i], x2 = sx[r0+2][i], x3 = sx[r0+3][i];
                a0.x=fmaf(x0,wv.x,a0.x); a0.y=fmaf(x0,wv.y,a0.y); a0.z=fmaf(x0,wv.z,a0.z); a0.w=fmaf(x0,wv.w,a0.w);
                a1.x=fmaf(x1,wv.x,a1.x); a1.y=fmaf(x1,wv.y,a1.y); a1.z=fmaf(x1,wv.z,a1.z); a1.w=fmaf(x1,wv.w,a1.w);
                a2.x=fmaf(x2,wv.x,a2.x); a2.y=fmaf(x2,wv.y,a2.y); a2.z=fmaf(x2,wv.z,a2.z); a2.w=fmaf(x2,wv.w,a2.w);
                a3.x=fmaf(x3,wv.x,a3.x); a3.y=fmaf(x3,wv.y,a3.y); a3.z=fmaf(x3,wv.z,a3.z); a3.w=fmaf(x3,wv.w,a3.w);
            }
            #pragma unroll 8
            for (int i = 0; i < Hd; i++) {
                float4 wv = w4[(Hd + i) * 16];
                float x0 = sh[r0][i], x1 = sh[r0+1][i], x2 = sh[r0+2][i], x3 = sh[r0+3][i];
                a0.x=fmaf(x0,wv.x,a0.x); a0.y=fmaf(x0,wv.y,a0.y); a0.z=fmaf(x0,wv.z,a0.z); a0.w=fmaf(x0,wv.w,a0.w);
                a1.x=fmaf(x1,wv.x,a1.x); a1.y=fmaf(x1,wv.y,a1.y); a1.z=fmaf(x1,wv.z,a1.z); a1.w=fmaf(x1,wv.w,a1.w);
                a2.x=fmaf(x2,wv.x,a2.x); a2.y=fmaf(x2,wv.y,a2.y); a2.z=fmaf(x2,wv.z,a2.z); a2.w=fmaf(x2,wv.w,a2.w);
                a3.x=fmaf(x3,wv.x,a3.x); a3.y=fmaf(x3,wv.y,a3.y); a3.z=fmaf(x3,wv.z,a3.z); a3.w=fmaf(x3,wv.w,a3.w);
            }
            float* d0 = &S_H1(r0, n, o0);   float* d1 = &S_H1(r0+1, n, o0);
            float* d2 = &S_H1(r0+2, n, o0); float* d3 = &S_H1(r0+3, n, o0);
            d0[0]=fmaxf(a0.x,0.f); d0[1]=fmaxf(a0.y,0.f); d0[2]=fmaxf(a0.z,0.f); d0[3]=fmaxf(a0.w,0.f);
            d1[0]=fmaxf(a1.x,0.f); d1[1]=fmaxf(a1.y,0.f); d1[2]=fmaxf(a1.z,0.f); d1[3]=fmaxf(a1.w,0.f);
            d2[0]=fmaxf(a2.x,0.f); d2[1]=fmaxf(a2.y,0.f); d2[2]=fmaxf(a2.z,0.f); d2[3]=fmaxf(a2.w,0.f);
            d3[0]=fmaxf(a3.x,0.f); d3[1]=fmaxf(a3.y,0.f); d3[2]=fmaxf(a3.z,0.f); d3[3]=fmaxf(a3.w,0.f);
        }
        __syncthreads();

        // ---- wait for eps slice t ----
        if (tid == 0) {
            while (atomicAdd(&g_done[t], 0) < EPS_T_BLOCKS) __nanosleep(200);
            __threadfence();
        }
        __syncthreads();

        // ---- S2+S5: m_post, KL (with register m_prior), z ----
        if (tid < 128) {
            float mpA0=0,mpA1=0,mpA2=0,mpA3=0, mpB0=0,mpB1=0,mpB2=0,mpB3=0;
            for (int n = 0; n < NZv; n++) {
                float4 bb = *(const float4*)(bp2 + n * Hd + cc);
                float4 aA = bb, aB = bb;
                const float4* w4 = (const float4*)(Wp2 + (size_t)n * 4096 + cc);
                #pragma unroll 8
                for (int o = 0; o < Hd; o++) {
                    float4 wv = w4[o * 16];
                    float hA = S_H1(rA, n, o), hB = S_H1(rA+1, n, o);
                    aA.x=fmaf(hA,wv.x,aA.x); aA.y=fmaf(hA,wv.y,aA.y); aA.z=fmaf(hA,wv.z,aA.z); aA.w=fmaf(hA,wv.w,aA.w);
                    aB.x=fmaf(hB,wv.x,aB.x); aB.y=fmaf(hB,wv.y,aB.y); aB.z=fmaf(hB,wv.z,aB.z); aB.w=fmaf(hB,wv.w,aB.w);
                }
                float g = gpost[n];
                mpA0=fmaf(g,aA.x,mpA0); mpA1=fmaf(g,aA.y,mpA1); mpA2=fmaf(g,aA.z,mpA2); mpA3=fmaf(g,aA.w,mpA3);
                mpB0=fmaf(g,aB.x,mpB0); mpB1=fmaf(g,aB.y,mpB1); mpB2=fmaf(g,aB.z,mpB2); mpB3=fmaf(g,aB.w,mpB3);
            }
            const float* epA = g_eps + ((size_t)t * Bn + row0 + rA) * Hd + cc;
            const float* epB = epA + Hd;
            float mpa[4] = {mpA0, mpA1, mpA2, mpA3};
            float mqa[4] = {mqA0, mqA1, mqA2, mqA3};
            float mpb[4] = {mpB0, mpB1, mpB2, mpB3};
            float mqb[4] = {mqB0, mqB1, mqB2, mqB3};
            #pragma unroll
            for (int q = 0; q < 4; q++) {
                float pm = fmaxf(mpa[q], 0.f), qm = fmaxf(mqa[q], 0.f);
                float ps = softplusf(mpa[q]), qs = softplusf(mqa[q]);
                float d = pm - qm;
                klA += logf(qs / ps) + (ps * ps + d * d) / (2.0f * qs * qs) - 0.5f;
                S_Z(rA, cc + q) = fmaf(ps, epA[q], pm);
            }
            #pragma unroll
            for (int q = 0; q < 4; q++) {
                float pm = fmaxf(mpb[q], 0.f), qm = fmaxf(mqb[q], 0.f);
                float ps = softplusf(mpb[q]), qs = softplusf(mqb[q]);
                float d = pm - qm;
                klB += logf(qs / ps) + (ps * ps + d * d) / (2.0f * qs * qs) - 0.5f;
                S_Z(rA + 1, cc + q) = fmaf(ps, epB[q], pm);
            }
        }
        __syncthreads();

        // ---- S6: phi_z ----
        {
            float4 a = *(const float4*)(b_z + c0);
            const float4* w4 = (const float4*)(W_z + c0);
            #pragma unroll 8
            for (int i = 0; i < Hd; i++) {
                float xv = S_Z(rT, i);
                float4 wv = w4[i * 16];
                a.x = fmaf(xv, wv.x, a.x); a.y = fmaf(xv, wv.y, a.y);
                a.z = fmaf(xv, wv.z, a.z); a.w = fmaf(xv, wv.w, a.w);
            }
            S_PZ(rT, c0)   = fmaxf(a.x, 0.f); S_PZ(rT, c0+1) = fmaxf(a.y, 0.f);
            S_PZ(rT, c0+2) = fmaxf(a.z, 0.f); S_PZ(rT, c0+3) = fmaxf(a.w, 0.f);
        }
        __syncthreads();

        // ---- S7/S8: GRU in two 8-row passes (gi/gh overlay h1) ----
        #pragma unroll
        for (int pass = 0; pass < 2; pass++) {
            int rb = pass * 8;
            for (int u = tid; u < 384; u += 256) {
                if (u < 192) {
                    int r2 = u / 48, k0i = (u % 48) * 4;
                    int r0 = rb + r2 * 2;
                    const float4* w4 = (const float4*)(W_ih + k0i);
                    float4 bb = *(const float4*)(b_ih + k0i);
                    float4 a0 = bb, a1 = bb;
                    #pragma unroll 8
                    for (int i = 0; i < Hd; i++) {
                        float xa = sx[r0][i], xb = sx[r0+1][i];
                        float4 wv = w4[i * 48];
                        a0.x=fmaf(xa,wv.x,a0.x); a0.y=fmaf(xa,wv.y,a0.y); a0.z=fmaf(xa,wv.z,a0.z); a0.w=fmaf(xa,wv.w,a0.w);
                        a1.x=fmaf(xb,wv.x,a1.x); a1.y=fmaf(xb,wv.y,a1.y); a1.z=fmaf(xb,wv.z,a1.z); a1.w=fmaf(xb,wv.w,a1.w);
                    }
                    #pragma unroll 8
                    for (int i = 0; i < Hd; i++) {
                        float xa = S_PZ(r0, i), xb = S_PZ(r0+1, i);
                        float4 wv = w4[(Hd + i) * 48];
                        a0.x=fmaf(xa,wv.x,a0.x); a0.y=fmaf(xa,wv.y,a0.y); a0.z=fmaf(xa,wv.z,a0.z); a0.w=fmaf(xa,wv.w,a0.w);
                        a1.x=fmaf(xb,wv.x,a1.x); a1.y=fmaf(xb,wv.y,a1.y); a1.z=fmaf(xb,wv.z,a1.z); a1.w=fmaf(xb,wv.w,a1.w);
                    }
                    *(float4*)&S_GI(r2 * 2, k0i)     = a0;
                    *(float4*)&S_GI(r2 * 2 + 1, k0i) = a1;
                } else {
                    int gu = u - 192;
                    int r2 = gu / 48, k0i = (gu % 48) * 4;
                    int r0 = rb + r2 * 2;
                    const float4* w4 = (const float4*)(W_hh + k0i);
                    float4 bb = *(const float4*)(b_hh + k0i);
                    float4 a0 = bb, a1 = bb;
                    #pragma unroll 8
                    for (int i = 0; i < Hd; i++) {
                        float xa = sh[r0][i], xb = sh[r0+1][i];
                        float4 wv = w4[i * 48];
                        a0.x=fmaf(xa,wv.x,a0.x); a0.y=fmaf(xa,wv.y,a0.y); a0.z=fmaf(xa,wv.z,a0.z); a0.w=fmaf(xa,wv.w,a0.w);
                        a1.x=fmaf(xb,wv.x,a1.x); a1.y=fmaf(xb,wv.y,a1.y); a1.z=fmaf(xb,wv.z,a1.z); a1.w=fmaf(xb,wv.w,a1.w);
                    }
                    *(float4*)&S_GH(r2 * 2, k0i)     = a0;
                    *(float4*)&S_GH(r2 * 2 + 1, k0i) = a1;
                }
            }
            __syncthreads();
            for (int idx = tid; idx < 512; idx += 256) {
                int lr = idx >> 6, j = idx & 63;
                int r = rb + lr;
                float ir = S_GI(lr, j), iz = S_GI(lr, Hd + j), in_ = S_GI(lr, 2 * Hd + j);
                float hr = S_GH(lr, j), hz = S_GH(lr, Hd + j), hn  = S_GH(lr, 2 * Hd + j);
                float rg = sigmoidf(ir + hr);
                float zz = sigmoidf(iz + hz);
                float nn = tanhf(fmaf(rg, hn, in_));
                sh[r][j] = (1.0f - zz) * nn + zz * sh[r][j];
            }
            __syncthreads();
        }
    }

    // ---------- KL write (per-row reduce over 16-thread groups) ----------
    #pragma unroll
    for (int off = 8; off; off >>= 1) {
        klA += __shfl_xor_sync(0xFFFFFFFFu, klA, off);
        klB += __shfl_xor_sync(0xFFFFFFFFu, klB, off);
    }
    if (tid < 128 && (tid & 15) == 0) {
        g_kld[row0 + rA]     = klA;
        g_kld[row0 + rA + 1] = klB;
    }

    // ---------- epilogue ----------
    // prior h1
    for (int u = tid; u < 4 * NZv * 16; u += 256) {
        int rg = u / 80, rem = u % 80;
        int n = rem >> 4, o0 = (rem & 15) * 4;
        int r0 = rg * 4;
        const float4* w4 = (const float4*)(Wq1 + (size_t)n * 4096 + o0);
        float4 bb = *(const float4*)(bq1 + n * Hd + o0);
        float4 a0 = bb, a1 = bb, a2 = bb, a3 = bb;
        #pragma unroll 8
        for (int i = 0; i < Hd; i++) {
            float4 wv = w4[i * 16];
            float x0 = sh[r0][i], x1 = sh[r0+1][i], x2 = sh[r0+2][i], x3 = sh[r0+3][i];
            a0.x=fmaf(x0,wv.x,a0.x); a0.y=fmaf(x0,wv.y,a0.y); a0.z=fmaf(x0,wv.z,a0.z); a0.w=fmaf(x0,wv.w,a0.w);
            a1.x=fmaf(x1,wv.x,a1.x); a1.y=fmaf(x1,wv.y,a1.y); a1.z=fmaf(x1,wv.z,a1.z); a1.w=fmaf(x1,wv.w,a1.w);
            a2.x=fmaf(x2,wv.x,a2.x); a2.y=fmaf(x2,wv.y,a2.y); a2.z=fmaf(x2,wv.z,a2.z); a2.w=fmaf(x2,wv.w,a2.w);
            a3.x=fmaf(x3,wv.x,a3.x); a3.y=fmaf(x3,wv.y,a3.y); a3.z=fmaf(x3,wv.z,a3.z); a3.w=fmaf(x3,wv.w,a3.w);
        }
        float* d0 = &S_H1(r0, n, o0);   float* d1 = &S_H1(r0+1, n, o0);
        float* d2 = &S_H1(r0+2, n, o0); float* d3 = &S_H1(r0+3, n, o0);
        d0[0]=fmaxf(a0.x,0.f); d0[1]=fmaxf(a0.y,0.f); d0[2]=fmaxf(a0.z,0.f); d0[3]=fmaxf(a0.w,0.f);
        d1[0]=fmaxf(a1.x,0.f); d1[1]=fmaxf(a1.y,0.f); d1[2]=fmaxf(a1.z,0.f); d1[3]=fmaxf(a1.w,0.f);
        d2[0]=fmaxf(a2.x,0.f); d2[1]=fmaxf(a2.y,0.f); d2[2]=fmaxf(a2.z,0.f); d2[3]=fmaxf(a2.w,0.f);
        d3[0]=fmaxf(a3.x,0.f); d3[1]=fmaxf(a3.y,0.f); d3[2]=fmaxf(a3.z,0.f); d3[3]=fmaxf(a3.w,0.f);
    }
    if (tid == 0) {
        while (atomicAdd(&g_done[Tn], 0) < EPS_T_BLOCKS) __nanosleep(200);
        __threadfence();
    }
    __syncthreads();
    // m_prior -> z (t = Tn)
    if (tid < 128) {
        float m0=0,m1=0,m2=0,m3=0, n0=0,n1=0,n2=0,n3=0;
        for (int n = 0; n < NZv; n++) {
            float4 bb = *(const float4*)(bq2 + n * Hd + cc);
            float4 aA = bb, aB = bb;
            const float4* w4 = (const float4*)(Wq2 + (size_t)n * 4096 + cc);
            #pragma unroll 8
            for (int o = 0; o < Hd; o++) {
                float4 wv = w4[o * 16];
                float hA = S_H1(rA, n, o), hB = S_H1(rA+1, n, o);
                aA.x=fmaf(hA,wv.x,aA.x); aA.y=fmaf(hA,wv.y,aA.y); aA.z=fmaf(hA,wv.z,aA.z); aA.w=fmaf(hA,wv.w,aA.w);
                aB.x=fmaf(hB,wv.x,aB.x); aB.y=fmaf(hB,wv.y,aB.y); aB.z=fmaf(hB,wv.z,aB.z); aB.w=fmaf(hB,wv.w,aB.w);
            }
            float g = gprior[n];
            m0=fmaf(g,aA.x,m0); m1=fmaf(g,aA.y,m1); m2=fmaf(g,aA.z,m2); m3=fmaf(g,aA.w,m3);
            n0=fmaf(g,aB.x,n0); n1=fmaf(g,aB.y,n1); n2=fmaf(g,aB.z,n2); n3=fmaf(g,aB.w,n3);
        }
        const float* epA = g_eps + ((size_t)Tn * Bn + row0 + rA) * Hd + cc;
        const float* epB = epA + Hd;
        float ma[4] = {m0, m1, m2, m3}, mb[4] = {n0, n1, n2, n3};
        #pragma unroll
        for (int q = 0; q < 4; q++) {
            S_Z(rA, cc + q)     = fmaf(softplusf(ma[q]), epA[q], fmaxf(ma[q], 0.f));
            S_Z(rA + 1, cc + q) = fmaf(softplusf(mb[q]), epB[q], fmaxf(mb[q], 0.f));
        }
    }
    __syncthreads();
    // phi_z
    {
        float4 a = *(const float4*)(b_z + c0);
        const float4* w4 = (const float4*)(W_z + c0);
        #pragma unroll 8
        for (int i = 0; i < Hd; i++) {
            float xv = S_Z(rT, i);
            float4 wv = w4[i * 16];
            a.x = fmaf(xv, wv.x, a.x); a.y = fmaf(xv, wv.y, a.y);
            a.z = fmaf(xv, wv.z, a.z); a.w = fmaf(xv, wv.w, a.w);
        }
        S_PZ(rT, c0)   = fmaxf(a.x, 0.f); S_PZ(rT, c0+1) = fmaxf(a.y, 0.f);
        S_PZ(rT, c0+2) = fmaxf(a.z, 0.f); S_PZ(rT, c0+3) = fmaxf(a.w, 0.f);
    }
    __syncthreads();
    // dec = relu([phi_z, h] @ W_dec + b_dec) -> sx
    {
        float4 a = *(const float4*)(b_dec + c0);
        const float4* w4 = (const float4*)(W_dec + c0);
        #pragma unroll 8
        for (int i = 0; i < Hd; i++) {
            float xv = S_PZ(rT, i);
            float4 wv = w4[i * 16];
            a.x = fmaf(xv, wv.x, a.x); a.y = fmaf(xv, wv.y, a.y);
            a.z = fmaf(xv, wv.z, a.z); a.w = fmaf(xv, wv.w, a.w);
        }
        #pragma unroll 8
        for (int i = 0; i < Hd; i++) {
            float xv = sh[rT][i];
            float4 wv = w4[(Hd + i) * 16];
            a.x = fmaf(xv, wv.x, a.x); a.y = fmaf(xv, wv.y, a.y);
            a.z = fmaf(xv, wv.z, a.z); a.w = fmaf(xv, wv.w, a.w);
        }
        sx[rT][c0]   = fmaxf(a.x, 0.f); sx[rT][c0+1] = fmaxf(a.y, 0.f);
        sx[rT][c0+2] = fmaxf(a.z, 0.f); sx[rT][c0+3] = fmaxf(a.w, 0.f);
    }
    __syncthreads();
    // logits
    for (int u = tid; u < Rr * ACTD; u += 256) {
        int r = u / ACTD, a = u % ACTD;
        float acc = b_a[a];
        #pragma unroll 8
        for (int j = 0; j < Hd; j++) acc = fmaf(sx[r][j], W_a[j * ACTD + a], acc);
        s_logit[r][a] = acc;
        out[(size_t)(row0 + r) * ACTD + a] = acc;
    }
    __syncthreads();
    // phi_logits -> S_Z
    {
        float4 a = *(const float4*)(b_act + c0);
        const float4* w4 = (const float4*)(W_act + c0);
        #pragma unroll
        for (int q = 0; q < ACTD; q++) {
            float xv = s_logit[rT][q];
            float4 wv = w4[q * 16];
            a.x = fmaf(xv, wv.x, a.x); a.y = fmaf(xv, wv.y, a.y);
            a.z = fmaf(xv, wv.z, a.z); a.w = fmaf(xv, wv.w, a.w);
        }
        S_Z(rT, c0)   = fmaxf(a.x, 0.f); S_Z(rT, c0+1) = fmaxf(a.y, 0.f);
        S_Z(rT, c0+2) = fmaxf(a.z, 0.f); S_Z(rT, c0+3) = fmaxf(a.w, 0.f);
    }
    __syncthreads();
    if (tid < Rr) {
        int r = tid;
        float acc = b_durd[0];
        #pragma unroll 8
        for (int j = 0; j < Hd; j++) acc = fmaf(S_Z(r, j), W_durd[j], acc);
        #pragma unroll 8
        for (int j = 0; j < Hd; j++) acc = fmaf(sx[r][j], W_durd[Hd + j], acc);
        out[(size_t)Bn * ACTD + row0 + r] = acc;
        out[(size_t)Bn * ACTD + Bn + row0 + r] = softplusf(acc);
    }

    // ---------- finalization ----------
    __threadfence();
    __syncthreads();
    if (tid == 0) atomicAdd(&g_scan_done, 1);

    if (sb == 0) {
        __shared__ float rs[256];
        if (tid == 0) {
            while (atomicAdd(&g_scan_done, 0) < SCAN_BLOCKS) __nanosleep(200);
            __threadfence();
        }
        __syncthreads();
        rs[tid] = g_kld[tid] + g_kld[tid + 256] + g_kld[tid + 512] + g_kld[tid + 768];
        __syncthreads();
        for (int st = 128; st > 0; st >>= 1) {
            if (tid < st) rs[tid] += rs[tid + st];
            __syncthreads();
        }
        if (tid == 0) out[(size_t)Bn * ACTD + 2 * Bn] = rs[0] * (1.0f / Bn);
        if (tid <= Tn) g_done[tid] = 0;
        if (tid == 0) g_scan_done = 0;
    }
#undef S_INP
#undef S_Z
#undef S_PZ
#undef S_H1
#undef S_GI
#undef S_GH
}

// ============================================================================
// fused kernel: blocks [0,64) = scan (wave-1 resident), rest = eps
// ============================================================================
__global__ void __launch_bounds__(256) fused_kernel(
    const int* __restrict__ acts, const float* __restrict__ durs,
    const float* __restrict__ W_act, const float* __restrict__ b_act,
    const float* __restrict__ W_dur, const float* __restrict__ b_dur,
    const float* __restrict__ W_x,  const float* __restrict__ b_x,
    const float* __restrict__ W_z,  const float* __restrict__ b_z,
    const float* __restrict__ Wp1,  const float* __restrict__ bp1,
    const float* __restrict__ Wp2,  const float* __restrict__ bp2,
    const float* __restrict__ Wq1,  const float* __restrict__ bq1,
    const float* __restrict__ Wq2,  const float* __restrict__ bq2,
    const float* __restrict__ W_dec,const float* __restrict__ b_dec,
    const float* __restrict__ W_a,  const float* __restrict__ b_a,
    const float* __restrict__ W_durd,const float* __restrict__ b_durd,
    const float* __restrict__ W_ih, const float* __restrict__ W_hh,
    const float* __restrict__ b_ih, const float* __restrict__ b_hh,
    const float* __restrict__ gpost,const float* __restrict__ gprior,
    float* __restrict__ out)
{
    if (blockIdx.x >= SCAN_BLOCKS) {
        eps_role(blockIdx.x - SCAN_BLOCKS);
    } else {
        scan_role(blockIdx.x,
                  acts, durs, W_act, b_act, W_dur, b_dur, W_x, b_x, W_z, b_z,
                  Wp1, bp1, Wp2, bp2, Wq1, bq1, Wq2, bq2, W_dec, b_dec,
                  W_a, b_a, W_durd, b_durd, W_ih, W_hh, b_ih, b_hh,
                  gpost, gprior, out);
    }
}

// ---------------- launch ----------------
extern "C" void kernel_launch(void* const* d_in, const int* in_sizes, int n_in,
                              void* d_out, int out_size) {
    const int*   acts   = (const int*)  d_in[0];
    const float* durs   = (const float*)d_in[1];
    const float* W_act  = (const float*)d_in[2];
    const float* b_act  = (const float*)d_in[3];
    const float* W_dur  = (const float*)d_in[4];
    const float* b_dur  = (const float*)d_in[5];
    const float* W_x    = (const float*)d_in[6];
    const float* b_x    = (const float*)d_in[7];
    const float* W_z    = (const float*)d_in[8];
    const float* b_z    = (const float*)d_in[9];
    const float* Wp1    = (const float*)d_in[10];
    const float* bp1    = (const float*)d_in[11];
    const float* Wp2    = (const float*)d_in[12];
    const float* bp2    = (const float*)d_in[13];
    const float* Wq1    = (const float*)d_in[14];
    const float* bq1    = (const float*)d_in[15];
    const float* Wq2    = (const float*)d_in[16];
    const float* bq2    = (const float*)d_in[17];
    const float* W_dec  = (const float*)d_in[18];
    const float* b_dec  = (const float*)d_in[19];
    const float* W_a    = (const float*)d_in[20];
    const float* b_a    = (const float*)d_in[21];
    const float* W_durd = (const float*)d_in[22];
    const float* b_durd = (const float*)d_in[23];
    const float* W_ih   = (const float*)d_in[24];
    const float* W_hh   = (const float*)d_in[25];
    const float* b_ih   = (const float*)d_in[26];
    const float* b_hh   = (const float*)d_in[27];
    const float* gpost  = (const float*)d_in[28];
    const float* gprior = (const float*)d_in[29];
    float* out = (float*)d_out;

    fused_kernel<<<SCAN_BLOCKS + EPS_TOTAL, 256>>>(
        acts, durs, W_act, b_act, W_dur, b_dur, W_x, b_x, W_z, b_z,
        Wp1, bp1, Wp2, bp2, Wq1, bq1, Wq2, bq2, W_dec, b_dec,
        W_a, b_a, W_durd, b_durd, W_ih, W_hh, b_ih, b_hh,
        gpost, gprior, out);
}

// round 12
// speedup vs baseline: 1.2863x; 1.1368x over previous
#include <cuda_runtime.h>

#define Bn 1024
#define Tn 128
#define Hd 64
#define NZv 5
#define ACTD 20
#define Rr 16
#define SCAN_BLOCKS 64
#define EPS_T_BLOCKS 256                     // 256 blocks x 256 threads = 65536 outputs per timestep
#define EPS_TOTAL ((Tn + 1) * EPS_T_BLOCKS)  // 33024 eps blocks

typedef unsigned long long ull;

// ---------------- device scratch (static allocation only) ----------------
__device__ float g_eps[(size_t)(Tn + 1) * Bn * Hd];     // (T+1,B,H)
__device__ float g_kld[SCAN_BLOCKS];                    // per-block partial sums
__device__ int   g_done[Tn + 1];                        // zero-init at load; reset by reducer
__device__ int   g_scan_done;                           // ditto
__device__ unsigned g_one = 1;   // runtime-opaque 1: forces adds onto IMAD (fma pipe)

// ---------------- f32x2 packed helpers ----------------
__device__ __forceinline__ ull pk2(float lo, float hi) {
    ull r; asm("mov.b64 %0, {%1, %2};" : "=l"(r) : "f"(lo), "f"(hi)); return r;
}
__device__ __forceinline__ void unpk2(ull v, float& lo, float& hi) {
    asm("mov.b64 {%0, %1}, %2;" : "=f"(lo), "=f"(hi) : "l"(v));
}
__device__ __forceinline__ ull pki2(unsigned lo, unsigned hi) {
    ull r; asm("mov.b64 %0, {%1, %2};" : "=l"(r) : "r"(lo), "r"(hi)); return r;
}
__device__ __forceinline__ ull fma2(ull a, ull b, ull c) {
    ull d; asm("fma.rn.f32x2 %0, %1, %2, %3;" : "=l"(d) : "l"(a), "l"(b), "l"(c)); return d;
}
__device__ __forceinline__ ull add2(ull a, ull b) {
    ull d; asm("add.rn.f32x2 %0, %1, %2;" : "=l"(d) : "l"(a), "l"(b)); return d;
}
__device__ __forceinline__ ull dup2(float x) { return pk2(x, x); }

// ---------------- math helpers ----------------
__device__ __forceinline__ float softplusf(float x) {
    return fmaxf(x, 0.0f) + log1pf(expf(-fabsf(x)));
}
__device__ __forceinline__ float sigmoidf(float x) {
    return 1.0f / (1.0f + expf(-x));
}
__device__ __forceinline__ unsigned imadd(unsigned a, unsigned b, unsigned one) {
    unsigned d;
    asm("mad.lo.u32 %0, %1, %2, %3;" : "=r"(d) : "r"(a), "r"(one), "r"(b));
    return d;
}
__device__ __forceinline__ float poly_main(float wk) {
    float p = 2.81022636e-08f;
    p = fmaf(p, wk, 3.43273939e-07f);
    p = fmaf(p, wk, -3.5233877e-06f);
    p = fmaf(p, wk, -4.39150654e-06f);
    p = fmaf(p, wk, 0.00021858087f);
    p = fmaf(p, wk, -0.00125372503f);
    p = fmaf(p, wk, -0.00417768164f);
    p = fmaf(p, wk, 0.246640727f);
    p = fmaf(p, wk, 1.50140941f);
    return p;
}
__device__ __forceinline__ float poly_tail(float w) {
    float ws = sqrtf(w) - 3.0f;
    float p = -0.000200214257f;
    p = fmaf(p, ws, 0.000100950558f);
    p = fmaf(p, ws, 0.00134934322f);
    p = fmaf(p, ws, -0.00367342844f);
    p = fmaf(p, ws, 0.00573950773f);
    p = fmaf(p, ws, -0.0076224613f);
    p = fmaf(p, ws, 0.00943887047f);
    p = fmaf(p, ws, 1.00167406f);
    p = fmaf(p, ws, 2.83297682f);
    return p;
}

// general threefry (prologue key fold only)
__device__ __forceinline__ uint2 threefry2x32(unsigned k0, unsigned k1,
                                              unsigned x0, unsigned x1) {
    unsigned ks2 = k0 ^ k1 ^ 0x1BD11BDAu;
#define TF_RND(r) { x0 += x1; x1 = __funnelshift_l(x1, x1, r); x1 ^= x0; }
    x0 += k0; x1 += k1;
    TF_RND(13) TF_RND(15) TF_RND(26) TF_RND(6)
    x0 += k1;  x1 += ks2 + 1u;
    TF_RND(17) TF_RND(29) TF_RND(16) TF_RND(24)
    x0 += ks2; x1 += k0 + 2u;
    TF_RND(13) TF_RND(15) TF_RND(26) TF_RND(6)
    x0 += k0;  x1 += k1 + 3u;
    TF_RND(17) TF_RND(29) TF_RND(16) TF_RND(24)
    x0 += k1;  x1 += ks2 + 4u;
    TF_RND(13) TF_RND(15) TF_RND(26) TF_RND(6)
    x0 += ks2; x1 += k0 + 5u;
#undef TF_RND
    uint2 r; r.x = x0; r.y = x1; return r;
}

// hot path: counter word0 == 0, adds on fma pipe; returns y0 ^ y1
__device__ __forceinline__ unsigned tf_xor(
    unsigned k0, unsigned k1, unsigned ks2,
    unsigned c1, unsigned c2, unsigned c3, unsigned c4, unsigned c5,
    unsigned e, unsigned k1d, unsigned one)
{
    unsigned x0 = k0;
    unsigned x1 = imadd(e, k1d, one);
#define TF_RND(r) { x0 = imadd(x1, x0, one); x1 = __funnelshift_l(x1, x1, r); x1 ^= x0; }
    TF_RND(13) TF_RND(15) TF_RND(26) TF_RND(6)
    x0 = imadd(k1, x0, one);  x1 = imadd(c1, x1, one);
    TF_RND(17) TF_RND(29) TF_RND(16) TF_RND(24)
    x0 = imadd(ks2, x0, one); x1 = imadd(c2, x1, one);
    TF_RND(13) TF_RND(15) TF_RND(26) TF_RND(6)
    x0 = imadd(k0, x0, one);  x1 = imadd(c3, x1, one);
    TF_RND(17) TF_RND(29) TF_RND(16) TF_RND(24)
    x0 = imadd(k1, x0, one);  x1 = imadd(c4, x1, one);
    TF_RND(13) TF_RND(15) TF_RND(26) TF_RND(6)
    x0 = imadd(ks2, x0, one); x1 = imadd(c5, x1, one);
#undef TF_RND
    return x0 ^ x1;
}

// mantissa word via funnel shift: (bits>>9) | 0x3F800000 in ONE SHF
__device__ __forceinline__ unsigned mant(unsigned bits) {
    return __funnelshift_r(bits, 0x7Fu, 9);
}

// ============================================================================
// EPS role (unchanged from R9)
// ============================================================================
__device__ __noinline__ void eps_role(int eb) {
    const int tid = threadIdx.x;
    const int t = eb >> 8;
    const unsigned bz = (unsigned)((eb & 255) * 256 + tid);
    const int gid = t * (Bn * Hd) + (int)bz;

    const unsigned one = g_one;
    uint2 kk = threefry2x32(0u, 42u, 0u, (unsigned)t);
    const unsigned k0 = kk.x, k1 = kk.y;
    const unsigned ks2 = k0 ^ k1 ^ 0x1BD11BDAu;
    const unsigned c1 = ks2 + 1u, c2 = k0 + 2u, c3 = k1 + 3u,
                   c4 = ks2 + 4u, c5 = k0 + 5u;
    const unsigned k1d0 = k1, k1d1 = k1 + 65536u,
                   k1d2 = k1 + 131072u, k1d3 = k1 + 196608u;

    const ull NEGONE2  = dup2(-1.0f);
    const ull TWO2     = dup2(2.0f);
    const ull NEGP2    = dup2(-0.99999994f);
    const ull NEGLN2_2 = dup2(-0.69314718f);
    const ull M2P5_2   = dup2(-2.5f);
    const ull P0 = dup2(2.81022636e-08f);
    const ull P1 = dup2(3.43273939e-07f);
    const ull P2 = dup2(-3.5233877e-06f);
    const ull P3 = dup2(-4.39150654e-06f);
    const ull P4 = dup2(0.00021858087f);
    const ull P5 = dup2(-0.00125372503f);
    const ull P6 = dup2(-0.00417768164f);
    const ull P7 = dup2(0.246640727f);
    const ull P8 = dup2(1.50140941f);

    ull sumA = 0ull, sumB = 0ull;
    unsigned e = bz;
    const unsigned step = 262144u;

    #pragma unroll 2
    for (int s = 0; s < 250; s++) {
        unsigned b0 = tf_xor(k0, k1, ks2, c1, c2, c3, c4, c5, e, k1d0, one);
        unsigned b1 = tf_xor(k0, k1, ks2, c1, c2, c3, c4, c5, e, k1d1, one);
        unsigned b2 = tf_xor(k0, k1, ks2, c1, c2, c3, c4, c5, e, k1d2, one);
        unsigned b3 = tf_xor(k0, k1, ks2, c1, c2, c3, c4, c5, e, k1d3, one);

        ull gA = pki2(mant(b0), mant(b1));
        ull gB = pki2(mant(b2), mant(b3));
        ull fA = add2(gA, NEGONE2);
        ull fB = add2(gB, NEGONE2);
        ull uA = fma2(fA, TWO2, NEGP2);
        ull uB = fma2(fB, TWO2, NEGP2);
        ull tA = fma2(uA, uA, NEGONE2);
        ull tB = fma2(uB, uB, NEGONE2);
        float t0, t1, t2, t3;
        unpk2(tA, t0, t1); unpk2(tB, t2, t3);
        float tm = fmaxf(fmaxf(t0, t1), fmaxf(t2, t3));

        if (__builtin_expect(tm >= -6.737947e-3f, 0)) {
            float u0, u1, u2, u3;
            unpk2(uA, u0, u1); unpk2(uB, u2, u3);
            float uu[4] = {u0, u1, u2, u3};
            float tt[4] = {t0, t1, t2, t3};
            float cc[4];
            #pragma unroll
            for (int i = 0; i < 4; i++) {
                float l = __log2f(-tt[i]);
                float w = l * -0.69314718f;
                float pv;
                if (w < 5.0f) pv = poly_main(fmaf(l, -0.69314718f, -2.5f));
                else          pv = poly_tail(w);
                cc[i] = pv * uu[i];
            }
            sumA = add2(sumA, pk2(cc[0], cc[1]));
            sumB = add2(sumB, pk2(cc[2], cc[3]));
        } else {
            float l0 = __log2f(-t0), l1 = __log2f(-t1);
            float l2 = __log2f(-t2), l3 = __log2f(-t3);
            ull wkA = fma2(pk2(l0, l1), NEGLN2_2, M2P5_2);
            ull wkB = fma2(pk2(l2, l3), NEGLN2_2, M2P5_2);
            ull pA = fma2(P0, wkA, P1);
            ull pB = fma2(P0, wkB, P1);
            pA = fma2(pA, wkA, P2);  pB = fma2(pB, wkB, P2);
            pA = fma2(pA, wkA, P3);  pB = fma2(pB, wkB, P3);
            pA = fma2(pA, wkA, P4);  pB = fma2(pB, wkB, P4);
            pA = fma2(pA, wkA, P5);  pB = fma2(pB, wkB, P5);
            pA = fma2(pA, wkA, P6);  pB = fma2(pB, wkB, P6);
            pA = fma2(pA, wkA, P7);  pB = fma2(pB, wkB, P7);
            pA = fma2(pA, wkA, P8);  pB = fma2(pB, wkB, P8);
            sumA = fma2(pA, uA, sumA);
            sumB = fma2(pB, uB, sumB);
        }
        e = imadd(step, e, one);
    }
    float s0, s1, s2, s3;
    unpk2(sumA, s0, s1); unpk2(sumB, s2, s3);
    g_eps[gid] = ((s0 + s1) + (s2 + s3)) * (1.41421356f * 0.001f);

    __threadfence();
    __syncthreads();
    if (tid == 0) atomicAdd(&g_done[t], 1);
}

// ============================================================================
// SCAN role: 16 rows/block, 64 blocks, R9-style low-register 2-row tiling
// ============================================================================
__device__ void scan_role(
    int sb,
    const int* __restrict__ acts, const float* __restrict__ durs,
    const float* __restrict__ W_act, const float* __restrict__ b_act,
    const float* __restrict__ W_dur, const float* __restrict__ b_dur,
    const float* __restrict__ W_x,  const float* __restrict__ b_x,
    const float* __restrict__ W_z,  const float* __restrict__ b_z,
    const float* __restrict__ Wp1,  const float* __restrict__ bp1,
    const float* __restrict__ Wp2,  const float* __restrict__ bp2,
    const float* __restrict__ Wq1,  const float* __restrict__ bq1,
    const float* __restrict__ Wq2,  const float* __restrict__ bq2,
    const float* __restrict__ W_dec,const float* __restrict__ b_dec,
    const float* __restrict__ W_a,  const float* __restrict__ b_a,
    const float* __restrict__ W_durd,const float* __restrict__ b_durd,
    const float* __restrict__ W_ih, const float* __restrict__ W_hh,
    const float* __restrict__ b_ih, const float* __restrict__ b_hh,
    const float* __restrict__ gpost,const float* __restrict__ gprior,
    float* __restrict__ out)
{
    __shared__ float sh[Rr][Hd];                 // 4KB
    __shared__ float sx[Rr][Hd];                 // 4KB phi_x / dec
    __shared__ float u_buf[Rr][2 * Hd];          // 8KB inp | (z, pz)
    __shared__ float u_big[Rr * NZv * Hd];       // 20KB h1 | (gi, gh for 8 rows)
    __shared__ float s_mp[Rr][Hd];               // 4KB m_post / phi_logits
    __shared__ float s_mq[Rr][Hd];               // 4KB m_prior
    __shared__ float s_logit[Rr][ACTD];          // 1.25KB

#define S_INP(r,c)  u_buf[r][c]
#define S_Z(r,j)    u_buf[r][j]
#define S_PZ(r,j)   u_buf[r][Hd + (j)]
#define S_H1(r,n,o) u_big[(((r) * NZv) + (n)) * Hd + (o)]
#define S_GI(lr,k)  u_big[(lr) * 192 + (k)]
#define S_GH(lr,k)  u_big[1536 + (lr) * 192 + (k)]

    const int tid = threadIdx.x;
    const int row0 = sb * Rr;
    float kl_acc = 0.0f;

    for (int idx = tid; idx < Rr * Hd; idx += 256) sh[idx >> 6][idx & 63] = 0.f;
    __syncthreads();

    for (int t = 0; t < Tn; t++) {
        // ---- S0: embed input ----
        for (int idx = tid; idx < Rr * 2 * Hd; idx += 256) {
            int r = idx >> 7, c = idx & 127;
            float v;
            if (c < Hd) {
                int a = acts[(row0 + r) * Tn + t];
                v = W_act[a * Hd + c] + b_act[c];
            } else {
                float du = durs[(row0 + r) * Tn + t];
                v = fmaf(du, W_dur[c - Hd], b_dur[c - Hd]);
            }
            S_INP(r, c) = fmaxf(v, 0.f);
        }
        __syncthreads();

        // ---- phi_x: units (r, j2) = 512 ----
        for (int u = tid; u < Rr * 32; u += 256) {
            int r = u >> 5, j0 = (u & 31) * 2;
            float a0 = b_x[j0], a1 = b_x[j0 + 1];
            const float2* w2 = (const float2*)(W_x + j0);
            #pragma unroll 8
            for (int i = 0; i < 2 * Hd; i++) {
                float xv = S_INP(r, i);
                float2 wv = w2[i * 32];
                a0 = fmaf(xv, wv.x, a0);
                a1 = fmaf(xv, wv.y, a1);
            }
            sx[r][j0]     = fmaxf(a0, 0.f);
            sx[r][j0 + 1] = fmaxf(a1, 0.f);
        }
        __syncthreads();

        // ---- S1: post h1 = relu([phi_x,h] @ Wp1 + bp1), 2-row tiles, 640 units ----
        for (int u = tid; u < 8 * NZv * 16; u += 256) {
            int r2 = u / 80, rem = u % 80;
            int n = rem >> 4, o0 = (rem & 15) * 4;
            int r0 = r2 * 2;
            const float4* w4 = (const float4*)(Wp1 + (size_t)n * 8192 + o0);
            float4 bb = *(const float4*)(bp1 + n * Hd + o0);
            float4 a0 = bb, a1 = bb;
            #pragma unroll 8
            for (int i = 0; i < Hd; i++) {
                float xa = sx[r0][i], xb = sx[r0 + 1][i];
                float4 wv = w4[i * 16];
                a0.x=fmaf(xa,wv.x,a0.x); a0.y=fmaf(xa,wv.y,a0.y); a0.z=fmaf(xa,wv.z,a0.z); a0.w=fmaf(xa,wv.w,a0.w);
                a1.x=fmaf(xb,wv.x,a1.x); a1.y=fmaf(xb,wv.y,a1.y); a1.z=fmaf(xb,wv.z,a1.z); a1.w=fmaf(xb,wv.w,a1.w);
            }
            #pragma unroll 8
            for (int i = 0; i < Hd; i++) {
                float xa = sh[r0][i], xb = sh[r0 + 1][i];
                float4 wv = w4[(Hd + i) * 16];
                a0.x=fmaf(xa,wv.x,a0.x); a0.y=fmaf(xa,wv.y,a0.y); a0.z=fmaf(xa,wv.z,a0.z); a0.w=fmaf(xa,wv.w,a0.w);
                a1.x=fmaf(xb,wv.x,a1.x); a1.y=fmaf(xb,wv.y,a1.y); a1.z=fmaf(xb,wv.z,a1.z); a1.w=fmaf(xb,wv.w,a1.w);
            }
            float* d0 = &S_H1(r0, n, o0);
            float* d1 = &S_H1(r0 + 1, n, o0);
            d0[0]=fmaxf(a0.x,0.f); d0[1]=fmaxf(a0.y,0.f); d0[2]=fmaxf(a0.z,0.f); d0[3]=fmaxf(a0.w,0.f);
            d1[0]=fmaxf(a1.x,0.f); d1[1]=fmaxf(a1.y,0.f); d1[2]=fmaxf(a1.z,0.f); d1[3]=fmaxf(a1.w,0.f);
        }
        __syncthreads();

        // ---- S2: m_post, units (r, z2) = 512 ----
        for (int u = tid; u < Rr * 32; u += 256) {
            int r = u >> 5, z0 = (u & 31) * 2;
            float m0 = 0.f, m1 = 0.f;
            for (int n = 0; n < NZv; n++) {
                float t0a = bp2[n * Hd + z0], t1a = bp2[n * Hd + z0 + 1];
                const float2* w2 = (const float2*)(Wp2 + (size_t)n * 4096 + z0);
                #pragma unroll 8
                for (int o = 0; o < Hd; o++) {
                    float hv = S_H1(r, n, o);
                    float2 wv = w2[o * 32];
                    t0a = fmaf(hv, wv.x, t0a);
                    t1a = fmaf(hv, wv.y, t1a);
                }
                float g = gpost[n];
                m0 = fmaf(g, t0a, m0);
                m1 = fmaf(g, t1a, m1);
            }
            s_mp[r][z0] = m0; s_mp[r][z0 + 1] = m1;
        }
        __syncthreads();

        // ---- S3: prior h1 = relu(h @ Wq1 + bq1), 640 units ----
        for (int u = tid; u < 8 * NZv * 16; u += 256) {
            int r2 = u / 80, rem = u % 80;
            int n = rem >> 4, o0 = (rem & 15) * 4;
            int r0 = r2 * 2;
            const float4* w4 = (const float4*)(Wq1 + (size_t)n * 4096 + o0);
            float4 bb = *(const float4*)(bq1 + n * Hd + o0);
            float4 a0 = bb, a1 = bb;
            #pragma unroll 8
            for (int i = 0; i < Hd; i++) {
                float xa = sh[r0][i], xb = sh[r0 + 1][i];
                float4 wv = w4[i * 16];
                a0.x=fmaf(xa,wv.x,a0.x); a0.y=fmaf(xa,wv.y,a0.y); a0.z=fmaf(xa,wv.z,a0.z); a0.w=fmaf(xa,wv.w,a0.w);
                a1.x=fmaf(xb,wv.x,a1.x); a1.y=fmaf(xb,wv.y,a1.y); a1.z=fmaf(xb,wv.z,a1.z); a1.w=fmaf(xb,wv.w,a1.w);
            }
            float* d0 = &S_H1(r0, n, o0);
            float* d1 = &S_H1(r0 + 1, n, o0);
            d0[0]=fmaxf(a0.x,0.f); d0[1]=fmaxf(a0.y,0.f); d0[2]=fmaxf(a0.z,0.f); d0[3]=fmaxf(a0.w,0.f);
            d1[0]=fmaxf(a1.x,0.f); d1[1]=fmaxf(a1.y,0.f); d1[2]=fmaxf(a1.z,0.f); d1[3]=fmaxf(a1.w,0.f);
        }
        __syncthreads();

        // ---- S4: m_prior ----
        for (int u = tid; u < Rr * 32; u += 256) {
            int r = u >> 5, z0 = (u & 31) * 2;
            float m0 = 0.f, m1 = 0.f;
            for (int n = 0; n < NZv; n++) {
                float t0a = bq2[n * Hd + z0], t1a = bq2[n * Hd + z0 + 1];
                const float2* w2 = (const float2*)(Wq2 + (size_t)n * 4096 + z0);
                #pragma unroll 8
                for (int o = 0; o < Hd; o++) {
                    float hv = S_H1(r, n, o);
                    float2 wv = w2[o * 32];
                    t0a = fmaf(hv, wv.x, t0a);
                    t1a = fmaf(hv, wv.y, t1a);
                }
                float g = gprior[n];
                m0 = fmaf(g, t0a, m0);
                m1 = fmaf(g, t1a, m1);
            }
            s_mq[r][z0] = m0; s_mq[r][z0 + 1] = m1;
        }
        __syncthreads();

        // ---- wait for eps slice t ----
        if (tid == 0) {
            while (atomicAdd(&g_done[t], 0) < EPS_T_BLOCKS) __nanosleep(200);
            __threadfence();
        }
        __syncthreads();

        // ---- S5: KL + z ----
        for (int u = tid; u < Rr * 32; u += 256) {
            int r = u >> 5, z0 = (u & 31) * 2;
            const float* ep = g_eps + ((size_t)t * Bn + row0 + r) * Hd + z0;
            #pragma unroll
            for (int q = 0; q < 2; q++) {
                float mp = s_mp[r][z0 + q], mq = s_mq[r][z0 + q];
                float pm = fmaxf(mp, 0.0f), qm = fmaxf(mq, 0.0f);
                float ps = softplusf(mp),   qs = softplusf(mq);
                float d = pm - qm;
                kl_acc += logf(qs / ps) + (ps * ps + d * d) / (2.0f * qs * qs) - 0.5f;
                S_Z(r, z0 + q) = fmaf(ps, ep[q], pm);
            }
        }
        __syncthreads();

        // ---- S6: phi_z ----
        for (int u = tid; u < Rr * 32; u += 256) {
            int r = u >> 5, j0 = (u & 31) * 2;
            float a0 = b_z[j0], a1 = b_z[j0 + 1];
            const float2* w2 = (const float2*)(W_z + j0);
            #pragma unroll 8
            for (int i = 0; i < Hd; i++) {
                float xv = S_Z(r, i);
                float2 wv = w2[i * 32];
                a0 = fmaf(xv, wv.x, a0);
                a1 = fmaf(xv, wv.y, a1);
            }
            S_PZ(r, j0)     = fmaxf(a0, 0.f);
            S_PZ(r, j0 + 1) = fmaxf(a1, 0.f);
        }
        __syncthreads();

        // ---- S7/S8: GRU, two 8-row passes (gi/gh overlay h1) ----
        #pragma unroll
        for (int pass = 0; pass < 2; pass++) {
            int rb = pass * 8;
            for (int u = tid; u < 384; u += 256) {
                if (u < 192) {
                    int r2 = u / 48, k0i = (u % 48) * 4;
                    int r0 = rb + r2 * 2;
                    const float4* w4 = (const float4*)(W_ih + k0i);
                    float4 bb = *(const float4*)(b_ih + k0i);
                    float4 a0 = bb, a1 = bb;
                    #pragma unroll 8
                    for (int i = 0; i < Hd; i++) {
                        float xa = sx[r0][i], xb = sx[r0 + 1][i];
                        float4 wv = w4[i * 48];
                        a0.x=fmaf(xa,wv.x,a0.x); a0.y=fmaf(xa,wv.y,a0.y); a0.z=fmaf(xa,wv.z,a0.z); a0.w=fmaf(xa,wv.w,a0.w);
                        a1.x=fmaf(xb,wv.x,a1.x); a1.y=fmaf(xb,wv.y,a1.y); a1.z=fmaf(xb,wv.z,a1.z); a1.w=fmaf(xb,wv.w,a1.w);
                    }
                    #pragma unroll 8
                    for (int i = 0; i < Hd; i++) {
                        float xa = S_PZ(r0, i), xb = S_PZ(r0 + 1, i);
                        float4 wv = w4[(Hd + i) * 48];
                        a0.x=fmaf(xa,wv.x,a0.x); a0.y=fmaf(xa,wv.y,a0.y); a0.z=fmaf(xa,wv.z,a0.z); a0.w=fmaf(xa,wv.w,a0.w);
                        a1.x=fmaf(xb,wv.x,a1.x); a1.y=fmaf(xb,wv.y,a1.y); a1.z=fmaf(xb,wv.z,a1.z); a1.w=fmaf(xb,wv.w,a1.w);
                    }
                    *(float4*)&S_GI(r2 * 2, k0i)     = a0;
                    *(float4*)&S_GI(r2 * 2 + 1, k0i) = a1;
                } else {
                    int gu = u - 192;
                    int r2 = gu / 48, k0i = (gu % 48) * 4;
                    int r0 = rb + r2 * 2;
                    const float4* w4 = (const float4*)(W_hh + k0i);
                    float4 bb = *(const float4*)(b_hh + k0i);
                    float4 a0 = bb, a1 = bb;
                    #pragma unroll 8
                    for (int i = 0; i < Hd; i++) {
                        float xa = sh[r0][i], xb = sh[r0 + 1][i];
                        float4 wv = w4[i * 48];
                        a0.x=fmaf(xa,wv.x,a0.x); a0.y=fmaf(xa,wv.y,a0.y); a0.z=fmaf(xa,wv.z,a0.z); a0.w=fmaf(xa,wv.w,a0.w);
                        a1.x=fmaf(xb,wv.x,a1.x); a1.y=fmaf(xb,wv.y,a1.y); a1.z=fmaf(xb,wv.z,a1.z); a1.w=fmaf(xb,wv.w,a1.w);
                    }
                    *(float4*)&S_GH(r2 * 2, k0i)     = a0;
                    *(float4*)&S_GH(r2 * 2 + 1, k0i) = a1;
                }
            }
            __syncthreads();
            for (int idx = tid; idx < 512; idx += 256) {
                int lr = idx >> 6, j = idx & 63;
                int r = rb + lr;
                float ir = S_GI(lr, j), iz = S_GI(lr, Hd + j), in_ = S_GI(lr, 2 * Hd + j);
                float hr = S_GH(lr, j), hz = S_GH(lr, Hd + j), hn  = S_GH(lr, 2 * Hd + j);
                float rg = sigmoidf(ir + hr);
                float zz = sigmoidf(iz + hz);
                float nn = tanhf(fmaf(rg, hn, in_));
                sh[r][j] = (1.0f - zz) * nn + zz * sh[r][j];
            }
            __syncthreads();
        }
    }

    // ---------- epilogue ----------
    // prior h1
    for (int u = tid; u < 8 * NZv * 16; u += 256) {
        int r2 = u / 80, rem = u % 80;
        int n = rem >> 4, o0 = (rem & 15) * 4;
        int r0 = r2 * 2;
        const float4* w4 = (const float4*)(Wq1 + (size_t)n * 4096 + o0);
        float4 bb = *(const float4*)(bq1 + n * Hd + o0);
        float4 a0 = bb, a1 = bb;
        #pragma unroll 8
        for (int i = 0; i < Hd; i++) {
            float xa = sh[r0][i], xb = sh[r0 + 1][i];
            float4 wv = w4[i * 16];
            a0.x=fmaf(xa,wv.x,a0.x); a0.y=fmaf(xa,wv.y,a0.y); a0.z=fmaf(xa,wv.z,a0.z); a0.w=fmaf(xa,wv.w,a0.w);
            a1.x=fmaf(xb,wv.x,a1.x); a1.y=fmaf(xb,wv.y,a1.y); a1.z=fmaf(xb,wv.z,a1.z); a1.w=fmaf(xb,wv.w,a1.w);
        }
        float* d0 = &S_H1(r0, n, o0);
        float* d1 = &S_H1(r0 + 1, n, o0);
        d0[0]=fmaxf(a0.x,0.f); d0[1]=fmaxf(a0.y,0.f); d0[2]=fmaxf(a0.z,0.f); d0[3]=fmaxf(a0.w,0.f);
        d1[0]=fmaxf(a1.x,0.f); d1[1]=fmaxf(a1.y,0.f); d1[2]=fmaxf(a1.z,0.f); d1[3]=fmaxf(a1.w,0.f);
    }
    if (tid == 0) {
        while (atomicAdd(&g_done[Tn], 0) < EPS_T_BLOCKS) __nanosleep(200);
        __threadfence();
    }
    __syncthreads();
    // m_prior -> z (t = Tn)
    for (int u = tid; u < Rr * 32; u += 256) {
        int r = u >> 5, z0 = (u & 31) * 2;
        float m0 = 0.f, m1 = 0.f;
        for (int n = 0; n < NZv; n++) {
            float t0a = bq2[n * Hd + z0], t1a = bq2[n * Hd + z0 + 1];
            const float2* w2 = (const float2*)(Wq2 + (size_t)n * 4096 + z0);
            #pragma unroll 8
            for (int o = 0; o < Hd; o++) {
                float hv = S_H1(r, n, o);
                float2 wv = w2[o * 32];
                t0a = fmaf(hv, wv.x, t0a);
                t1a = fmaf(hv, wv.y, t1a);
            }
            float g = gprior[n];
            m0 = fmaf(g, t0a, m0);
            m1 = fmaf(g, t1a, m1);
        }
        const float* ep = g_eps + ((size_t)Tn * Bn + row0 + r) * Hd + z0;
        S_Z(r, z0)     = fmaf(softplusf(m0), ep[0], fmaxf(m0, 0.f));
        S_Z(r, z0 + 1) = fmaf(softplusf(m1), ep[1], fmaxf(m1, 0.f));
    }
    __syncthreads();
    // phi_z
    for (int u = tid; u < Rr * 32; u += 256) {
        int r = u >> 5, j0 = (u & 31) * 2;
        float a0 = b_z[j0], a1 = b_z[j0 + 1];
        const float2* w2 = (const float2*)(W_z + j0);
        #pragma unroll 8
        for (int i = 0; i < Hd; i++) {
            float xv = S_Z(r, i);
            float2 wv = w2[i * 32];
            a0 = fmaf(xv, wv.x, a0);
            a1 = fmaf(xv, wv.y, a1);
        }
        S_PZ(r, j0)     = fmaxf(a0, 0.f);
        S_PZ(r, j0 + 1) = fmaxf(a1, 0.f);
    }
    __syncthreads();
    // dec -> sx
    for (int u = tid; u < Rr * 32; u += 256) {
        int r = u >> 5, j0 = (u & 31) * 2;
        float a0 = b_dec[j0], a1 = b_dec[j0 + 1];
        const float2* w2 = (const float2*)(W_dec + j0);
        #pragma unroll 8
        for (int i = 0; i < Hd; i++) {
            float xv = S_PZ(r, i);
            float2 wv = w2[i * 32];
            a0 = fmaf(xv, wv.x, a0);
            a1 = fmaf(xv, wv.y, a1);
        }
        #pragma unroll 8
        for (int i = 0; i < Hd; i++) {
            float xv = sh[r][i];
            float2 wv = w2[(Hd + i) * 32];
            a0 = fmaf(xv, wv.x, a0);
            a1 = fmaf(xv, wv.y, a1);
        }
        sx[r][j0]     = fmaxf(a0, 0.f);
        sx[r][j0 + 1] = fmaxf(a1, 0.f);
    }
    __syncthreads();
    // logits
    for (int u = tid; u < Rr * ACTD; u += 256) {
        int r = u / ACTD, a = u % ACTD;
        float acc = b_a[a];
        #pragma unroll 8
        for (int j = 0; j < Hd; j++) acc = fmaf(sx[r][j], W_a[j * ACTD + a], acc);
        s_logit[r][a] = acc;
        out[(size_t)(row0 + r) * ACTD + a] = acc;
    }
    __syncthreads();
    // phi_logits -> s_mp
    for (int u = tid; u < Rr * 32; u += 256) {
        int r = u >> 5, j0 = (u & 31) * 2;
        float a0 = b_act[j0], a1 = b_act[j0 + 1];
        const float2* w2 = (const float2*)(W_act + j0);
        #pragma unroll
        for (int a = 0; a < ACTD; a++) {
            float xv = s_logit[r][a];
            float2 wv = w2[a * 32];
            a0 = fmaf(xv, wv.x, a0);
            a1 = fmaf(xv, wv.y, a1);
        }
        s_mp[r][j0]     = fmaxf(a0, 0.f);
        s_mp[r][j0 + 1] = fmaxf(a1, 0.f);
    }
    __syncthreads();
    if (tid < Rr) {
        int r = tid;
        float acc = b_durd[0];
        #pragma unroll 8
        for (int j = 0; j < Hd; j++) acc = fmaf(s_mp[r][j], W_durd[j], acc);
        #pragma unroll 8
        for (int j = 0; j < Hd; j++) acc = fmaf(sx[r][j], W_durd[Hd + j], acc);
        out[(size_t)Bn * ACTD + row0 + r] = acc;
        out[(size_t)Bn * ACTD + Bn + row0 + r] = softplusf(acc);
    }
    __syncthreads();

    // ---------- block-wide KL reduction -> per-block partial ----------
    {
        float* rs = (float*)u_buf;   // u_buf free now
        rs[tid] = kl_acc;
        __syncthreads();
        for (int st = 128; st > 0; st >>= 1) {
            if (tid < st) rs[tid] += rs[tid + st];
            __syncthreads();
        }
        if (tid == 0) g_kld[sb] = rs[0];
    }

    // ---------- finalization ----------
    __threadfence();
    __syncthreads();
    if (tid == 0) atomicAdd(&g_scan_done, 1);

    if (sb == 0) {
        float* rs = (float*)u_buf;
        if (tid == 0) {
            while (atomicAdd(&g_scan_done, 0) < SCAN_BLOCKS) __nanosleep(200);
            __threadfence();
        }
        __syncthreads();
        rs[tid] = (tid < SCAN_BLOCKS) ? g_kld[tid] : 0.f;
        __syncthreads();
        for (int st = 128; st > 0; st >>= 1) {
            if (tid < st) rs[tid] += rs[tid + st];
            __syncthreads();
        }
        if (tid == 0) out[(size_t)Bn * ACTD + 2 * Bn] = rs[0] * (1.0f / Bn);
        if (tid <= Tn) g_done[tid] = 0;
        if (tid == 0) g_scan_done = 0;
    }
#undef S_INP
#undef S_Z
#undef S_PZ
#undef S_H1
#undef S_GI
#undef S_GH
}

// ============================================================================
// fused kernel: blocks [0,64) = scan (wave-1 resident), rest = eps
// ============================================================================
__global__ void __launch_bounds__(256) fused_kernel(
    const int* __restrict__ acts, const float* __restrict__ durs,
    const float* __restrict__ W_act, const float* __restrict__ b_act,
    const float* __restrict__ W_dur, const float* __restrict__ b_dur,
    const float* __restrict__ W_x,  const float* __restrict__ b_x,
    const float* __restrict__ W_z,  const float* __restrict__ b_z,
    const float* __restrict__ Wp1,  const float* __restrict__ bp1,
    const float* __restrict__ Wp2,  const float* __restrict__ bp2,
    const float* __restrict__ Wq1,  const float* __restrict__ bq1,
    const float* __restrict__ Wq2,  const float* __restrict__ bq2,
    const float* __restrict__ W_dec,const float* __restrict__ b_dec,
    const float* __restrict__ W_a,  const float* __restrict__ b_a,
    const float* __restrict__ W_durd,const float* __restrict__ b_durd,
    const float* __restrict__ W_ih, const float* __restrict__ W_hh,
    const float* __restrict__ b_ih, const float* __restrict__ b_hh,
    const float* __restrict__ gpost,const float* __restrict__ gprior,
    float* __restrict__ out)
{
    if (blockIdx.x >= SCAN_BLOCKS) {
        eps_role(blockIdx.x - SCAN_BLOCKS);
    } else {
        scan_role(blockIdx.x,
                  acts, durs, W_act, b_act, W_dur, b_dur, W_x, b_x, W_z, b_z,
                  Wp1, bp1, Wp2, bp2, Wq1, bq1, Wq2, bq2, W_dec, b_dec,
                  W_a, b_a, W_durd, b_durd, W_ih, W_hh, b_ih, b_hh,
                  gpost, gprior, out);
    }
}

// ---------------- launch ----------------
extern "C" void kernel_launch(void* const* d_in, const int* in_sizes, int n_in,
                              void* d_out, int out_size) {
    const int*   acts   = (const int*)  d_in[0];
    const float* durs   = (const float*)d_in[1];
    const float* W_act  = (const float*)d_in[2];
    const float* b_act  = (const float*)d_in[3];
    const float* W_dur  = (const float*)d_in[4];
    const float* b_dur  = (const float*)d_in[5];
    const float* W_x    = (const float*)d_in[6];
    const float* b_x    = (const float*)d_in[7];
    const float* W_z    = (const float*)d_in[8];
    const float* b_z    = (const float*)d_in[9];
    const float* Wp1    = (const float*)d_in[10];
    const float* bp1    = (const float*)d_in[11];
    const float* Wp2    = (const float*)d_in[12];
    const float* bp2    = (const float*)d_in[13];
    const float* Wq1    = (const float*)d_in[14];
    const float* bq1    = (const float*)d_in[15];
    const float* Wq2    = (const float*)d_in[16];
    const float* bq2    = (const float*)d_in[17];
    const float* W_dec  = (const float*)d_in[18];
    const float* b_dec  = (const float*)d_in[19];
    const float* W_a    = (const float*)d_in[20];
    const float* b_a    = (const float*)d_in[21];
    const float* W_durd = (const float*)d_in[22];
    const float* b_durd = (const float*)d_in[23];
    const float* W_ih   = (const float*)d_in[24];
    const float* W_hh   = (const float*)d_in[25];
    const float* b_ih   = (const float*)d_in[26];
    const float* b_hh   = (const float*)d_in[27];
    const float* gpost  = (const float*)d_in[28];
    const float* gprior = (const float*)d_in[29];
    float* out = (float*)d_out;

    fused_kernel<<<SCAN_BLOCKS + EPS_TOTAL, 256>>>(
        acts, durs, W_act, b_act, W_dur, b_dur, W_x, b_x, W_z, b_z,
        Wp1, bp1, Wp2, bp2, Wq1, bq1, Wq2, bq2, W_dec, b_dec,
        W_a, b_a, W_durd, b_durd, W_ih, W_hh, b_ih, b_hh,
        gpost, gprior, out);
}